// round 15
// baseline (speedup 1.0000x reference)
#include <cuda_runtime.h>
#include <cuda_fp16.h>
#include <math.h>
#include <stdint.h>

// ---------------- problem constants ----------------
#define B_   4
#define S1_  768
#define S2_  64
#define S_   832
#define D0_  2048
#define F0_  16384
#define D1_  1024
#define F1_  4096
#define H_   8
#define HD_  256
#define EPS_ 1e-6f
#define MASK_H_  -60000.0f
#define NQKV_ (H_*HD_ + 2*HD_)   // 2560

// ---------------- scratch (device globals) ----------------
__device__ float g_mod_in[B_*2*D1_];
__device__ float g_mod_post[B_*2*D1_];
__device__ float g_q[(size_t)B_*S_*H_*HD_];
__device__ float g_k[B_*S_*HD_];
__device__ float g_v[B_*S_*HD_];
__device__ float g_r0[B_*S1_*D0_];
__device__ float g_r1[B_*S2_*D1_];
__device__ int   g_pos[B_*S_];
__device__ int   g_cs[B_*S_];
// fp16 operands
__device__ __half g_hc0[(size_t)B_*S1_*D0_];
__device__ __half g_hc1[B_*S2_*D1_];
__device__ __half g_qr[(size_t)B_*H_*S_*HD_];
__device__ __half g_kr[B_*S_*HD_];
__device__ __half g_vt[B_*HD_*S_];
__device__ __half g_ph[(size_t)B_*H_*S_*S_];
__device__ __half g_atth[(size_t)B_*S_*H_*HD_];
__device__ __half g_yc0[(size_t)B_*S1_*D0_];
__device__ __half g_yc1[B_*S2_*D1_];
__device__ __half g_gu0hg[(size_t)B_*S1_*F0_];
__device__ __half g_gu0h[(size_t)B_*S1_*F0_];
__device__ __half g_gu1h2[(size_t)B_*S2_*2*F1_];
__device__ __half g_gu1h[B_*S2_*F1_];
// transposed fp16 weights [N, K]
__device__ __half g_wqkv0t[(size_t)NQKV_*2048];
__device__ __half g_wqkv1t[(size_t)NQKV_*1024];
__device__ __half g_wo0t[(size_t)2048*2048];
__device__ __half g_wg0t[(size_t)16384*2048];
__device__ __half g_wu0t[(size_t)16384*2048];
__device__ __half g_wd0t[(size_t)2048*16384];
__device__ __half g_wo1t[(size_t)1024*2048];
__device__ __half g_wgu1t[(size_t)2*4096*1024];
__device__ __half g_wd1t[(size_t)1024*4096];

// ---------------- helpers ----------------
__device__ __forceinline__ float gelu_tanh(float x) {
    float x3 = x * x * x;
    return 0.5f * x * (1.0f + tanhf(0.79788456080286535588f * (x + 0.044715f * x3)));
}
__device__ __forceinline__ uint32_t smem_u32(const void* p) {
    uint32_t a;
    asm("{ .reg .u64 t; cvta.to.shared.u64 t, %1; cvt.u32.u64 %0, t; }" : "=r"(a) : "l"(p));
    return a;
}
#define CP_ASYNC16(sm, gm) \
    asm volatile("cp.async.cg.shared.global [%0], [%1], 16;" :: "r"(sm), "l"(gm))
#define CP_COMMIT() asm volatile("cp.async.commit_group;")
#define CP_WAIT(n)  asm volatile("cp.async.wait_group %0;" :: "n"(n))

__device__ __forceinline__ void ldsm_x4(uint32_t* r, uint32_t addr) {
    asm volatile("ldmatrix.sync.aligned.m8n8.x4.shared.b16 {%0,%1,%2,%3}, [%4];"
                 : "=r"(r[0]), "=r"(r[1]), "=r"(r[2]), "=r"(r[3]) : "r"(addr));
}
__device__ __forceinline__ void mma_f16(float* c, const uint32_t* a, uint32_t b0, uint32_t b1) {
    asm volatile("mma.sync.aligned.m16n8k16.row.col.f32.f16.f16.f32 "
                 "{%0,%1,%2,%3}, {%4,%5,%6,%7}, {%8,%9}, {%0,%1,%2,%3};"
                 : "+f"(c[0]), "+f"(c[1]), "+f"(c[2]), "+f"(c[3])
                 : "r"(a[0]), "r"(a[1]), "r"(a[2]), "r"(a[3]), "r"(b0), "r"(b1));
}
__device__ __forceinline__ uint32_t sw_addr(uint32_t base, int row, int chunk) {
    return base + (uint32_t)(((row << 3) + (chunk ^ (row & 7))) << 4);
}

// ---------------- epilogue modes ----------------
#define EPI_NONE        0
#define EPI_SCORES_H    1
#define EPI_RES         2
#define EPI_RES_GATE    3
#define EPI_H           4
#define EPI_GELUMUL_HH  5
#define EPI_QKV         6
#define EPI_RES_ATOMIC  7   // atomicAdd fp32 C; chunk zr==0 also adds aux

// ---------------- TC fp16 GEMM: C[M,N] = A[M,Kp slice of Kstride] * Bt^T ----------------
struct TcP {
    const __half* A; const __half* Bt;
    float* C; __half* Ch;
    float* Ck; float* Cv;
    const float* aux; const __half* auxh; const float* gvec;
    const int *cs, *pad;
    size_t zA1, zA2, zB1, zB2, zC1, zC2, zAux, zGv;
    int zdiv;
    int gstride, gdiv;
    int maskStride; float scale;
    int M, N, Kp, Kstride, epi;
    int rpb, obatch, ldc;
};

#define TC_STAGES 3
#define TC_STAGE_BYTES 32768
#define TC_SMEM (TC_STAGES * TC_STAGE_BYTES)

__global__ __launch_bounds__(256) void tc_gemm_kernel(TcP p) {
    extern __shared__ char dsm[];
    uint32_t sbase = smem_u32(dsm);

    int tid  = threadIdx.x;
    int wid  = tid >> 5;
    int lane = tid & 31;
    int wm = wid >> 2;
    int wn = wid & 3;

    int m0 = blockIdx.y * 128;
    int n0 = blockIdx.x * 128;
    int z  = blockIdx.z;
    int zb = z / p.zdiv;
    int zr = z - zb * p.zdiv;

    const __half* Ab = p.A  + (size_t)zb * p.zA1 + (size_t)zr * p.zA2;
    const __half* Bb = p.Bt + (size_t)zb * p.zB1 + (size_t)zr * p.zB2;

    int kc = tid & 7;
    int rb = tid >> 3;

    float acc[4][4][4];
    #pragma unroll
    for (int i = 0; i < 4; i++)
        #pragma unroll
        for (int j = 0; j < 4; j++)
            #pragma unroll
            for (int e = 0; e < 4; e++) acc[i][j][e] = 0.f;

    int nIter = p.Kp >> 6;

    auto issue = [&](int it) {
        int st = it % TC_STAGES;
        uint32_t sa = sbase + st * TC_STAGE_BYTES;
        uint32_t sb = sa + 16384;
        int k0 = it << 6;
        #pragma unroll
        for (int i = 0; i < 4; i++) {
            int row = rb + i * 32;
            int ra = m0 + row; if (ra > p.M - 1) ra = p.M - 1;
            CP_ASYNC16(sw_addr(sa, row, kc), Ab + (size_t)ra * p.Kstride + k0 + kc * 8);
            int rn = n0 + row; if (rn > p.N - 1) rn = p.N - 1;
            CP_ASYNC16(sw_addr(sb, row, kc), Bb + (size_t)rn * p.Kstride + k0 + kc * 8);
        }
        CP_COMMIT();
    };

    #pragma unroll
    for (int s = 0; s < TC_STAGES - 1; s++) issue(s);

    int grp = lane >> 3;
    int lr  = lane & 7;

    for (int it = 0; it < nIter; it++) {
        if (it + TC_STAGES - 1 < nIter) {
            issue(it + TC_STAGES - 1);
            CP_WAIT(TC_STAGES - 2);
        } else {
            CP_WAIT(0);
        }
        __syncthreads();

        int st = it % TC_STAGES;
        uint32_t sa = sbase + st * TC_STAGE_BYTES;
        uint32_t sb = sa + 16384;

        #pragma unroll
        for (int kb = 0; kb < 4; kb++) {
            int chA = 2 * kb + (grp >> 1);
            uint32_t a[4][4];
            #pragma unroll
            for (int mi = 0; mi < 4; mi++) {
                int row = wm * 64 + mi * 16 + (grp & 1) * 8 + lr;
                ldsm_x4(a[mi], sw_addr(sa, row, chA));
            }
            uint32_t bf[2][4];
            #pragma unroll
            for (int bi = 0; bi < 2; bi++) {
                int row = wn * 32 + bi * 16 + (grp & 1) * 8 + lr;
                ldsm_x4(bf[bi], sw_addr(sb, row, chA));
            }
            #pragma unroll
            for (int mi = 0; mi < 4; mi++)
                #pragma unroll
                for (int ni = 0; ni < 4; ni++) {
                    int bi = ni >> 1, wh = ni & 1;
                    mma_f16(acc[mi][ni], a[mi], bf[bi][wh], bf[bi][wh + 2]);
                }
        }
        __syncthreads();
    }

    // ---- epilogue ----
    const int* csb  = p.cs  ? p.cs  + (size_t)zb * p.maskStride : nullptr;
    const int* padb = p.pad ? p.pad + (size_t)zb * p.maskStride : nullptr;
    const float* auxz = p.aux ? p.aux + (size_t)zb * p.zAux : nullptr;
    const __half* auxhz = p.auxh ? p.auxh + (size_t)zb * p.zAux : nullptr;
    const float* gvz  = p.gvec ? p.gvec + (size_t)zb * p.zGv : nullptr;
    float* Cz = p.C + (size_t)zb * p.zC1 + (size_t)zr * p.zC2;
    __half* Chz = p.Ch + (size_t)zb * p.zC1 + (size_t)zr * p.zC2;
    int qrow = lane >> 2;
    int qcol = (lane & 3) * 2;
    #pragma unroll
    for (int mi = 0; mi < 4; mi++) {
        #pragma unroll
        for (int half_ = 0; half_ < 2; half_++) {
            int r = m0 + wm * 64 + mi * 16 + half_ * 8 + qrow;
            if (r >= p.M) continue;
            int orow = (r / p.rpb) * p.obatch + (r % p.rpb);
            #pragma unroll
            for (int ni = 0; ni < 4; ni++) {
                int col = n0 + wn * 32 + ni * 8 + qcol;
                if (col >= p.N) continue;
                float v0 = acc[mi][ni][half_ * 2 + 0];
                float v1 = acc[mi][ni][half_ * 2 + 1];
                if (p.epi == EPI_QKV) {
                    float2 ov = make_float2(v0, v1);
                    if (col < H_ * HD_)
                        *(float2*)&p.C[(size_t)orow * (H_ * HD_) + col] = ov;
                    else if (col < H_ * HD_ + HD_)
                        *(float2*)&p.Ck[(size_t)orow * HD_ + (col - H_ * HD_)] = ov;
                    else
                        *(float2*)&p.Cv[(size_t)orow * HD_ + (col - H_ * HD_ - HD_)] = ov;
                    continue;
                } else if (p.epi == EPI_H) {
                    __half2 hv; hv.x = __float2half(v0); hv.y = __float2half(v1);
                    *(__half2*)&Chz[(size_t)orow * p.ldc + col] = hv;
                    continue;
                } else if (p.epi == EPI_GELUMUL_HH) {
                    __half2 ah = *(const __half2*)&auxhz[(size_t)r * p.N + col];
                    __half2 hv;
                    hv.x = __float2half(gelu_tanh(__half2float(ah.x)) * v0);
                    hv.y = __float2half(gelu_tanh(__half2float(ah.y)) * v1);
                    *(__half2*)&Chz[(size_t)orow * p.ldc + col] = hv;
                    continue;
                } else if (p.epi == EPI_SCORES_H) {
                    int csr = csb[r];
                    bool okr = padb[r] != 0;
                    bool ok0 = (csb[col] <= csr) && okr && (padb[col] != 0);
                    bool ok1 = (csb[col + 1] <= csr) && okr && (padb[col + 1] != 0);
                    __half2 hv;
                    hv.x = __float2half(ok0 ? v0 * p.scale : MASK_H_);
                    hv.y = __float2half(ok1 ? v1 * p.scale : MASK_H_);
                    *(__half2*)&Chz[(size_t)orow * p.ldc + col] = hv;
                    continue;
                } else if (p.epi == EPI_RES_ATOMIC) {
                    if (zr == 0) {
                        float2 ax = *(const float2*)&auxz[(size_t)r * p.N + col];
                        v0 += ax.x; v1 += ax.y;
                    }
                    atomicAdd(&Cz[(size_t)orow * p.ldc + col], v0);
                    atomicAdd(&Cz[(size_t)orow * p.ldc + col + 1], v1);
                    continue;
                } else if (p.epi == EPI_RES) {
                    float2 ax = *(const float2*)&auxz[(size_t)r * p.N + col];
                    v0 += ax.x; v1 += ax.y;
                } else if (p.epi == EPI_RES_GATE) {
                    float2 ax = *(const float2*)&auxz[(size_t)r * p.N + col];
                    float2 gx = *(const float2*)&gvz[(size_t)(r / p.gdiv) * p.gstride + col];
                    v0 = ax.x + gx.x * v0;
                    v1 = ax.y + gx.y * v1;
                }
                *(float2*)&Cz[(size_t)orow * p.ldc + col] = make_float2(v0, v1);
            }
        }
    }
}

// ---------------- multi-weight transpose fp32 -> fp16 ----------------
#define WT_MAX 8
struct WtEntry { const float* src; __half* dst; int K, N, nx, blkOff; };
struct WtP { WtEntry e[WT_MAX]; int cnt; };

__global__ void wtrans_multi_kernel(WtP p) {
    int bx = blockIdx.x;
    int i = p.cnt - 1;
    while (i > 0 && bx < p.e[i].blkOff) i--;
    WtEntry e = p.e[i];
    int local = bx - e.blkOff;
    int n0 = (local % e.nx) * 32;
    int k0 = (local / e.nx) * 64;

    __shared__ float t[64][33];
    int tx = threadIdx.x, ty = threadIdx.y;
    #pragma unroll
    for (int j = 0; j < 8; j++)
        t[ty + j * 8][tx] = e.src[(size_t)(k0 + ty + j * 8) * e.N + n0 + tx];
    __syncthreads();
    #pragma unroll
    for (int j = 0; j < 4; j++) {
        int nl = j * 8 + ty;
        __half2 hv;
        hv.x = __float2half(t[2 * tx][nl]);
        hv.y = __float2half(t[2 * tx + 1][nl]);
        *(__half2*)&e.dst[(size_t)(n0 + nl) * e.K + k0 + 2 * tx] = hv;
    }
}

// batched V transpose (z over B)
__global__ void wtrans_kernel(const float* __restrict__ W, __half* __restrict__ out,
                              int K, int N, size_t inZ, size_t outZ) {
    W   += blockIdx.z * inZ;
    out += blockIdx.z * outZ;
    __shared__ float t[64][33];
    int k0 = blockIdx.y * 64, n0 = blockIdx.x * 32;
    int tx = threadIdx.x, ty = threadIdx.y;
    #pragma unroll
    for (int i = 0; i < 8; i++)
        t[ty + i * 8][tx] = W[(size_t)(k0 + ty + i * 8) * N + n0 + tx];
    __syncthreads();
    #pragma unroll
    for (int j = 0; j < 4; j++) {
        int nl = j * 8 + ty;
        __half2 hv;
        hv.x = __float2half(t[2 * tx][nl]);
        hv.y = __float2half(t[2 * tx + 1][nl]);
        *(__half2*)&out[(size_t)(n0 + nl) * K + k0 + 2 * tx] = hv;
    }
}

// merged RoPE (Q then K ranges) -> fp16
__global__ void rope_qk_kernel(const float* __restrict__ q, const float* __restrict__ k,
                               const int* __restrict__ pos,
                               __half* __restrict__ qr, __half* __restrict__ kr) {
    const long NQ = (long)B_ * H_ * S_ * 128;
    const long NK = (long)B_ * S_ * 128;
    long idx = blockIdx.x * (long)blockDim.x + threadIdx.x;
    if (idx >= NQ + NK) return;
    if (idx < NQ) {
        int i = (int)(idx & 127);
        long t = idx >> 7;
        int s = (int)(t % S_); t /= S_;
        int h = (int)(t % H_);
        int b = (int)(t / H_);
        const float* base = q + ((size_t)(b * S_ + s) * H_ + h) * HD_;
        float x1 = base[i], x2 = base[i + 128];
        float f = (float)pos[b * S_ + s] * expf(-((float)i / 128.0f) * 9.210340371976184f);
        float sn, c; sincosf(f, &sn, &c);
        __half* ob = qr + ((size_t)(b * H_ + h) * S_ + s) * HD_;
        ob[i]       = __float2half(x1 * c - x2 * sn);
        ob[i + 128] = __float2half(x2 * c + x1 * sn);
    } else {
        idx -= NQ;
        int i = (int)(idx & 127);
        long t = idx >> 7;
        int s = (int)(t % S_);
        int b = (int)(t / S_);
        const float* base = k + (size_t)(b * S_ + s) * HD_;
        float x1 = base[i], x2 = base[i + 128];
        float f = (float)pos[b * S_ + s] * expf(-((float)i / 128.0f) * 9.210340371976184f);
        float sn, c; sincosf(f, &sn, &c);
        __half* ob = kr + (size_t)(b * S_ + s) * HD_;
        ob[i]       = __float2half(x1 * c - x2 * sn);
        ob[i + 128] = __float2half(x2 * c + x1 * sn);
    }
}

// elementwise gelu-mul (stream-1 fused gate|up)
__global__ void ew_gelumul_kernel(const __half* __restrict__ gu, __half* __restrict__ out,
                                  int M, int F) {
    long idx = blockIdx.x * (long)blockDim.x + threadIdx.x;
    if (idx >= (long)M * F) return;
    int r = (int)(idx / F), j = (int)(idx % F);
    const __half* g = gu + (size_t)r * 2 * F;
    out[(size_t)r * F + j] =
        __float2half(gelu_tanh(__half2float(g[j])) * __half2float(g[F + j]));
}

// merged mod GEMV
__global__ void mod2_kernel(const float* __restrict__ cond,
                            const float* __restrict__ W0, const float* __restrict__ b0, float* __restrict__ o0,
                            const float* __restrict__ W1, const float* __restrict__ b1, float* __restrict__ o1,
                            int D, int N) {
    const float* W = blockIdx.z ? W1 : W0;
    const float* bias = blockIdx.z ? b1 : b0;
    float* out = blockIdx.z ? o1 : o0;
    __shared__ float red[256];
    int tid = threadIdx.x;
    int j = blockIdx.x * 64 + (tid & 63);
    int ks = tid >> 6;
    int b = blockIdx.y;
    const float* c = cond + (size_t)b * D;
    int kseg = D >> 2;
    int kbeg = ks * kseg;
    float s = 0.f;
    for (int kk = kbeg; kk < kbeg + kseg; kk++)
        s += c[kk] * W[(size_t)kk * N + j];
    red[tid] = s;
    __syncthreads();
    if (ks == 0)
        out[(size_t)b * N + j] = bias[j] + red[tid] + red[tid + 64] + red[tid + 128] + red[tid + 192];
}

// parallel prefix scan (block per batch)
__global__ void scan_par_kernel(const int* __restrict__ pad, const int* __restrict__ att,
                                int* __restrict__ pos, int* __restrict__ cs) {
    __shared__ int sp[1024];
    __shared__ int sa[1024];
    int b = blockIdx.x;
    int t = threadIdx.x;
    int vp = 0, va = 0;
    if (t < S_) {
        vp = pad[b * S_ + t];
        va = att[b * S_ + t];
    }
    sp[t] = vp; sa[t] = va;
    __syncthreads();
    #pragma unroll
    for (int off = 1; off < 1024; off <<= 1) {
        int ap = 0, aa = 0;
        if (t >= off) { ap = sp[t - off]; aa = sa[t - off]; }
        __syncthreads();
        sp[t] += ap; sa[t] += aa;
        __syncthreads();
    }
    if (t < S_) {
        pos[b * S_ + t] = sp[t] - 1;
        cs[b * S_ + t] = sa[t];
    }
}

// merged RMSNorm (two tensors, row-routed) -> fp16
__global__ void rmsnorm2_kernel(const float* __restrict__ xA, __half* __restrict__ oA,
                                const float* __restrict__ wA, int wsA, int DA, int rpbA, int MA,
                                const float* __restrict__ xB, __half* __restrict__ oB,
                                const float* __restrict__ wB, int wsB, int DB, int rpbB) {
    long row = blockIdx.x;
    const float* xp; __half* op; const float* wp; int D;
    if (row < MA) {
        xp = xA + row * (long)DA; op = oA + row * (long)DA;
        wp = wA + (size_t)(row / rpbA) * wsA; D = DA;
    } else {
        long r2 = row - MA;
        xp = xB + r2 * (long)DB; op = oB + r2 * (long)DB;
        wp = wB + (size_t)(r2 / rpbB) * wsB; D = DB;
    }
    float ss = 0.f;
    for (int i = threadIdx.x; i < D; i += blockDim.x) {
        float v = xp[i];
        ss += v * v;
    }
    __shared__ float red[256];
    red[threadIdx.x] = ss;
    __syncthreads();
    for (int s = 128; s > 0; s >>= 1) {
        if (threadIdx.x < s) red[threadIdx.x] += red[threadIdx.x + s];
        __syncthreads();
    }
    float r = rsqrtf(red[0] / (float)D + EPS_);
    for (int i = threadIdx.x; i < D; i += blockDim.x)
        op[i] = __float2half(xp[i] * r * (1.0f + wp[i]));
}

// row softmax on fp16 in-place
__global__ void softmax_h_kernel(__half* __restrict__ probs) {
    __half* p = probs + (size_t)blockIdx.x * S_;
    __shared__ float red[256];
    int tid = threadIdx.x;
    float loc[4];
    float m = -3.4e38f;
    for (int c = 0, i = tid; i < S_; i += 256, c++) {
        loc[c] = __half2float(p[i]);
        m = fmaxf(m, loc[c]);
    }
    red[tid] = m;
    __syncthreads();
    for (int s = 128; s > 0; s >>= 1) {
        if (tid < s) red[tid] = fmaxf(red[tid], red[tid + s]);
        __syncthreads();
    }
    m = red[0];
    __syncthreads();
    float sum = 0.f;
    for (int c = 0, i = tid; i < S_; i += 256, c++) {
        float e = expf(loc[c] - m);
        loc[c] = e;
        sum += e;
    }
    red[tid] = sum;
    __syncthreads();
    for (int s = 128; s > 0; s >>= 1) {
        if (tid < s) red[tid] += red[tid + s];
        __syncthreads();
    }
    float inv = 1.0f / red[0];
    for (int c = 0, i = tid; i < S_; i += 256, c++)
        p[i] = __float2half(loc[c] * inv);
}

// ---------------- host helper ----------------
struct TcArgs {
    const __half* A; const __half* Bt;
    float* C; __half* Ch = nullptr;
    int M = 0, N = 0, Kp = 0, epi = 0;
    const float* aux = nullptr;
    int rpb = 0, obatch = 0, ldc = 0;
    int zcount = 1, zdiv = 1;
    size_t zA1 = 0, zA2 = 0, zB1 = 0, zB2 = 0, zC1 = 0, zC2 = 0, zAux = 0, zGv = 0;
    const int* cs = nullptr; const int* pad = nullptr;
    int maskStride = 0; float scale = 1.0f;
    const float* gvec = nullptr; int gstride = 0, gdiv = 1;
    float* Ck = nullptr; float* Cv = nullptr;
    const __half* auxh = nullptr;
    int Kstride = 0;
};

static void launch_tc(const TcArgs& a) {
    cudaFuncSetAttribute(tc_gemm_kernel, cudaFuncAttributeMaxDynamicSharedMemorySize, TC_SMEM);
    TcP p;
    p.A = a.A; p.Bt = a.Bt; p.C = a.C; p.Ch = a.Ch; p.Ck = a.Ck; p.Cv = a.Cv;
    p.aux = a.aux; p.auxh = a.auxh; p.gvec = a.gvec;
    p.cs = a.cs; p.pad = a.pad;
    p.zA1 = a.zA1; p.zA2 = a.zA2; p.zB1 = a.zB1; p.zB2 = a.zB2;
    p.zC1 = a.zC1; p.zC2 = a.zC2; p.zAux = a.zAux; p.zGv = a.zGv;
    p.zdiv = a.zdiv; p.gstride = a.gstride; p.gdiv = a.gdiv;
    p.maskStride = a.maskStride; p.scale = a.scale;
    p.M = a.M; p.N = a.N; p.Kp = a.Kp; p.epi = a.epi;
    p.Kstride = a.Kstride ? a.Kstride : a.Kp;
    p.rpb = a.rpb ? a.rpb : a.M; p.obatch = a.obatch; p.ldc = a.ldc ? a.ldc : a.N;
    dim3 grid((a.N + 127) / 128, (a.M + 127) / 128, a.zcount);
    tc_gemm_kernel<<<grid, 256, TC_SMEM>>>(p);
}

struct WtBuild {
    WtP p;
    int total = 0;
    WtBuild() { p.cnt = 0; }
    void add(const float* src, __half* dst, int K, int N) {
        WtEntry& e = p.e[p.cnt++];
        e.src = src; e.dst = dst; e.K = K; e.N = N;
        e.nx = N / 32;
        e.blkOff = total;
        total += (N / 32) * (K / 64);
    }
    void launch(cudaStream_t st) {
        wtrans_multi_kernel<<<total, dim3(32, 8), 0, st>>>(p);
    }
};

extern "C" void kernel_launch(void* const* d_in, const int* in_sizes, int n_in,
                              void* d_out, int out_size) {
    const float* x0         = (const float*)d_in[0];
    const float* x1         = (const float*)d_in[1];
    const float* cond1      = (const float*)d_in[2];
    const float* w_q0       = (const float*)d_in[3];
    const float* w_k0       = (const float*)d_in[4];
    const float* w_v0       = (const float*)d_in[5];
    const float* w_o0       = (const float*)d_in[6];
    const float* norm1_w0   = (const float*)d_in[7];
    const float* norm2_w0   = (const float*)d_in[8];
    const float* w_gate0    = (const float*)d_in[9];
    const float* w_up0      = (const float*)d_in[10];
    const float* w_down0    = (const float*)d_in[11];
    const float* w_q1       = (const float*)d_in[12];
    const float* w_k1       = (const float*)d_in[13];
    const float* w_v1       = (const float*)d_in[14];
    const float* w_o1       = (const float*)d_in[15];
    const float* ada_in_w1  = (const float*)d_in[16];
    const float* ada_in_b1  = (const float*)d_in[17];
    const float* ada_post_w1= (const float*)d_in[18];
    const float* ada_post_b1= (const float*)d_in[19];
    const float* w_gate1    = (const float*)d_in[20];
    const float* w_up1      = (const float*)d_in[21];
    const float* w_down1    = (const float*)d_in[22];
    const int*   pad_masks  = (const int*)d_in[23];
    const int*   att_masks  = (const int*)d_in[24];

    float* out0 = (float*)d_out;
    float* out1 = out0 + (size_t)B_ * S1_ * D0_;

    float *modin, *modpost, *q, *k, *v, *r0, *r1;
    int *pos, *cs;
    __half *hc0, *hc1, *qr, *kr, *vt, *ph, *atth, *yc0, *yc1;
    __half *gu0hg, *gu0h, *gu1h2, *gu1h;
    __half *wqkv0t, *wqkv1t, *wo0t, *wg0t, *wu0t, *wd0t, *wo1t, *wgu1t, *wd1t;
    cudaGetSymbolAddress((void**)&modin, g_mod_in);
    cudaGetSymbolAddress((void**)&modpost, g_mod_post);
    cudaGetSymbolAddress((void**)&q, g_q);
    cudaGetSymbolAddress((void**)&k, g_k);
    cudaGetSymbolAddress((void**)&v, g_v);
    cudaGetSymbolAddress((void**)&r0, g_r0);
    cudaGetSymbolAddress((void**)&r1, g_r1);
    cudaGetSymbolAddress((void**)&pos, g_pos);
    cudaGetSymbolAddress((void**)&cs, g_cs);
    cudaGetSymbolAddress((void**)&hc0, g_hc0);
    cudaGetSymbolAddress((void**)&hc1, g_hc1);
    cudaGetSymbolAddress((void**)&qr, g_qr);
    cudaGetSymbolAddress((void**)&kr, g_kr);
    cudaGetSymbolAddress((void**)&vt, g_vt);
    cudaGetSymbolAddress((void**)&ph, g_ph);
    cudaGetSymbolAddress((void**)&atth, g_atth);
    cudaGetSymbolAddress((void**)&yc0, g_yc0);
    cudaGetSymbolAddress((void**)&yc1, g_yc1);
    cudaGetSymbolAddress((void**)&gu0hg, g_gu0hg);
    cudaGetSymbolAddress((void**)&gu0h, g_gu0h);
    cudaGetSymbolAddress((void**)&gu1h2, g_gu1h2);
    cudaGetSymbolAddress((void**)&gu1h, g_gu1h);
    cudaGetSymbolAddress((void**)&wqkv0t, g_wqkv0t);
    cudaGetSymbolAddress((void**)&wqkv1t, g_wqkv1t);
    cudaGetSymbolAddress((void**)&wo0t, g_wo0t);
    cudaGetSymbolAddress((void**)&wg0t, g_wg0t);
    cudaGetSymbolAddress((void**)&wu0t, g_wu0t);
    cudaGetSymbolAddress((void**)&wd0t, g_wd0t);
    cudaGetSymbolAddress((void**)&wo1t, g_wo1t);
    cudaGetSymbolAddress((void**)&wgu1t, g_wgu1t);
    cudaGetSymbolAddress((void**)&wd1t, g_wd1t);

    const int M0 = B_ * S1_;   // 3072
    const int M1 = B_ * S2_;   // 256

    // ---- side stream (created once, outside capture) ----
    static cudaStream_t s2 = nullptr;
    static cudaEvent_t evFork = nullptr, evJoin = nullptr;
    if (!s2) {
        cudaStreamCreate(&s2);
        cudaEventCreateWithFlags(&evFork, cudaEventDisableTiming);
        cudaEventCreateWithFlags(&evJoin, cudaEventDisableTiming);
    }

    // zero-init split-K accumulation targets (async, capturable)
    cudaMemsetAsync(r0, 0, (size_t)M0 * D0_ * sizeof(float), 0);
    cudaMemsetAsync(out0, 0, (size_t)M0 * D0_ * sizeof(float), 0);

    // fork: merged conversion of late-consumed weights on side stream
    cudaEventRecord(evFork, 0);
    cudaStreamWaitEvent(s2, evFork, 0);
    {
        WtBuild wb;
        wb.add(w_o0,    wo0t, H_ * HD_, D0_);
        wb.add(w_gate0, wg0t, D0_, F0_);
        wb.add(w_up0,   wu0t, D0_, F0_);
        wb.add(w_down0, wd0t, F0_, D0_);
        wb.add(w_o1,    wo1t, H_ * HD_, D1_);
        wb.add(w_gate1, wgu1t, D1_, F1_);
        wb.add(w_up1,   wgu1t + (size_t)F1_ * D1_, D1_, F1_);
        wb.add(w_down1, wd1t, F1_, D1_);
        wb.launch(s2);
    }
    cudaEventRecord(evJoin, s2);

    // main stream: merged QKV weight conversion
    {
        WtBuild wb;
        wb.add(w_q0, wqkv0t, D0_, H_ * HD_);
        wb.add(w_k0, wqkv0t + (size_t)(H_ * HD_) * D0_, D0_, HD_);
        wb.add(w_v0, wqkv0t + (size_t)(H_ * HD_ + HD_) * D0_, D0_, HD_);
        wb.add(w_q1, wqkv1t, D1_, H_ * HD_);
        wb.add(w_k1, wqkv1t + (size_t)(H_ * HD_) * D1_, D1_, HD_);
        wb.add(w_v1, wqkv1t + (size_t)(H_ * HD_ + HD_) * D1_, D1_, HD_);
        wb.launch(0);
    }

    // ---- adaLN modulation (merged) + parallel scans ----
    {
        dim3 mg(2 * D1_ / 64, B_, 2);
        mod2_kernel<<<mg, 256>>>(cond1, ada_in_w1, ada_in_b1, modin,
                                 ada_post_w1, ada_post_b1, modpost, D1_, 2 * D1_);
    }
    scan_par_kernel<<<B_, 1024>>>(pad_masks, att_masks, pos, cs);

    // ---- input norms (merged) -> fp16 ----
    rmsnorm2_kernel<<<M0 + M1, 256>>>(x0, hc0, norm1_w0, 0, D0_, S1_, M0,
                                      x1, hc1, modin, 2 * D1_, D1_, S2_);

    // ---- fused QKV projections ----
    { TcArgs a{hc0, wqkv0t, q, nullptr, M0, NQKV_, D0_, EPI_QKV};
      a.Ck = k; a.Cv = v;
      a.rpb = S1_; a.obatch = S_; launch_tc(a); }
    { TcArgs a{hc1, wqkv1t, q + (size_t)S1_ * H_ * HD_, nullptr, M1, NQKV_, D1_, EPI_QKV};
      a.Ck = k + (size_t)S1_ * HD_; a.Cv = v + (size_t)S1_ * HD_;
      a.rpb = S2_; a.obatch = S_; launch_tc(a); }

    // ---- merged RoPE + V transpose ----
    {
        long ntot = (long)B_ * H_ * S_ * 128 + (long)B_ * S_ * 128;
        rope_qk_kernel<<<(unsigned)((ntot + 255) / 256), 256>>>(q, k, pos, qr, kr);
        dim3 vg(HD_ / 32, S_ / 64, B_);
        wtrans_kernel<<<vg, dim3(32, 8)>>>(v, vt, S_, HD_, (size_t)S_ * HD_, (size_t)HD_ * S_);
    }

    // ---- scores = Q K^T * scale, masked -> fp16 ph (z = B*H) ----
    { TcArgs a{qr, kr, nullptr, ph, S_, S_, HD_, EPI_SCORES_H};
      a.zcount = B_ * H_; a.zdiv = H_;
      a.zA1 = (size_t)H_ * S_ * HD_; a.zA2 = (size_t)S_ * HD_;
      a.zB1 = (size_t)S_ * HD_;
      a.zC1 = (size_t)H_ * S_ * S_; a.zC2 = (size_t)S_ * S_;
      a.cs = cs; a.pad = pad_masks; a.maskStride = S_; a.scale = 0.0625f;
      launch_tc(a); }

    softmax_h_kernel<<<B_ * H_ * S_, 256>>>(ph);

    // ---- PV (z = B*H) -> atth fp16 ----
    { TcArgs a{ph, vt, nullptr, atth, S_, HD_, S_, EPI_H};
      a.ldc = H_ * HD_;
      a.zcount = B_ * H_; a.zdiv = H_;
      a.zA1 = (size_t)H_ * S_ * S_; a.zA2 = (size_t)S_ * S_;
      a.zB1 = (size_t)HD_ * S_;
      a.zC1 = (size_t)S_ * H_ * HD_; a.zC2 = (size_t)HD_;
      launch_tc(a); }

    // join: side-stream weight conversions before o-projections / MLPs
    cudaStreamWaitEvent(0, evJoin, 0);

    // ---- o0 projection: split-K x2, z = (batch, kchunk), atomic accumulate into r0 ----
    { TcArgs a{atth, wo0t, r0, nullptr, S1_, D0_, (H_ * HD_) / 2, EPI_RES_ATOMIC};
      a.Kstride = H_ * HD_;
      a.aux = x0;
      a.zcount = 2 * B_; a.zdiv = 2;
      a.zA1 = (size_t)S_ * H_ * HD_; a.zA2 = (size_t)(H_ * HD_) / 2;
      a.zB2 = (size_t)(H_ * HD_) / 2;
      a.zC1 = (size_t)S1_ * D0_; a.zAux = (size_t)S1_ * D0_;
      launch_tc(a); }
    { TcArgs a{atth + (size_t)S1_ * H_ * HD_, wo1t, r1, nullptr, S2_, D1_, H_ * HD_, EPI_RES_GATE};
      a.aux = x1;
      a.zcount = B_;
      a.zA1 = (size_t)S_ * H_ * HD_; a.zC1 = (size_t)S2_ * D1_; a.zAux = (size_t)S2_ * D1_;
      a.gvec = modin + D1_; a.zGv = (size_t)2 * D1_; a.gdiv = S2_; a.gstride = 0;
      launch_tc(a); }

    // ---- post norms (merged) -> fp16 ----
    rmsnorm2_kernel<<<M0 + M1, 256>>>(r0, yc0, norm2_w0, 0, D0_, S1_, M0,
                                      r1, yc1, modpost, 2 * D1_, D1_, S2_);

    // ---- MLP stream 0 ----
    { TcArgs a{yc0, wg0t, nullptr, gu0hg, M0, F0_, D0_, EPI_H}; launch_tc(a); }
    { TcArgs a{yc0, wu0t, nullptr, gu0h, M0, F0_, D0_, EPI_GELUMUL_HH}; a.auxh = gu0hg; launch_tc(a); }
    // down0: split-K x4, atomic accumulate into out0 (zeroed), chunk 0 adds r0
    { TcArgs a{gu0h, wd0t, out0, nullptr, M0, D0_, F0_ / 4, EPI_RES_ATOMIC};
      a.Kstride = F0_;
      a.aux = r0;
      a.zcount = 4; a.zdiv = 4;
      a.zA2 = (size_t)F0_ / 4;
      a.zB2 = (size_t)F0_ / 4;
      launch_tc(a); }

    // ---- MLP stream 1 ----
    { TcArgs a{yc1, wgu1t, nullptr, gu1h2, M1, 2 * F1_, D1_, EPI_H}; launch_tc(a); }
    {
        long n = (long)M1 * F1_;
        ew_gelumul_kernel<<<(unsigned)((n + 255) / 256), 256>>>(gu1h2, gu1h, M1, F1_);
    }
    { TcArgs a{gu1h, wd1t, out1, nullptr, M1, D1_, F1_, EPI_RES_GATE};
      a.aux = r1;
      a.gvec = modpost + D1_; a.gstride = 2 * D1_; a.gdiv = S2_;
      launch_tc(a); }
}

// round 16
// speedup vs baseline: 1.0746x; 1.0746x over previous
#include <cuda_runtime.h>
#include <cuda_fp16.h>
#include <math.h>
#include <stdint.h>

// ---------------- problem constants ----------------
#define B_   4
#define S1_  768
#define S2_  64
#define S_   832
#define D0_  2048
#define F0_  16384
#define D1_  1024
#define F1_  4096
#define H_   8
#define HD_  256
#define EPS_ 1e-6f
#define MASK_H_  -60000.0f
#define NQKV_ (H_*HD_ + 2*HD_)   // 2560

// ---------------- scratch (device globals) ----------------
__device__ float g_mod_in[B_*2*D1_];
__device__ float g_mod_post[B_*2*D1_];
__device__ float g_q[(size_t)B_*S_*H_*HD_];
__device__ float g_k[B_*S_*HD_];
__device__ float g_v[B_*S_*HD_];
__device__ float g_r0[B_*S1_*D0_];
__device__ float g_r1[B_*S2_*D1_];
__device__ int   g_pos[B_*S_];
__device__ int   g_cs[B_*S_];
// fp16 operands
__device__ __half g_hc0[(size_t)B_*S1_*D0_];
__device__ __half g_hc1[B_*S2_*D1_];
__device__ __half g_qr[(size_t)B_*H_*S_*HD_];
__device__ __half g_kr[B_*S_*HD_];
__device__ __half g_vt[B_*HD_*S_];
__device__ __half g_ph[(size_t)B_*H_*S_*S_];
__device__ __half g_atth[(size_t)B_*S_*H_*HD_];
__device__ __half g_yc0[(size_t)B_*S1_*D0_];
__device__ __half g_yc1[B_*S2_*D1_];
__device__ __half g_gu0hg[(size_t)B_*S1_*F0_];
__device__ __half g_gu0h[(size_t)B_*S1_*F0_];
__device__ __half g_gu1h2[(size_t)B_*S2_*2*F1_];
__device__ __half g_gu1h[B_*S2_*F1_];
// transposed fp16 weights [N, K]
__device__ __half g_wqkv0t[(size_t)NQKV_*2048];
__device__ __half g_wqkv1t[(size_t)NQKV_*1024];
__device__ __half g_wo0t[(size_t)2048*2048];
__device__ __half g_wg0t[(size_t)16384*2048];
__device__ __half g_wu0t[(size_t)16384*2048];
__device__ __half g_wd0t[(size_t)2048*16384];
__device__ __half g_wo1t[(size_t)1024*2048];
__device__ __half g_wgu1t[(size_t)2*4096*1024];
__device__ __half g_wd1t[(size_t)1024*4096];

// ---------------- helpers ----------------
__device__ __forceinline__ float gelu_tanh(float x) {
    float x3 = x * x * x;
    return 0.5f * x * (1.0f + tanhf(0.79788456080286535588f * (x + 0.044715f * x3)));
}
__device__ __forceinline__ uint32_t smem_u32(const void* p) {
    uint32_t a;
    asm("{ .reg .u64 t; cvta.to.shared.u64 t, %1; cvt.u32.u64 %0, t; }" : "=r"(a) : "l"(p));
    return a;
}
#define CP_ASYNC16(sm, gm) \
    asm volatile("cp.async.cg.shared.global [%0], [%1], 16;" :: "r"(sm), "l"(gm))
#define CP_COMMIT() asm volatile("cp.async.commit_group;")
#define CP_WAIT(n)  asm volatile("cp.async.wait_group %0;" :: "n"(n))

__device__ __forceinline__ void ldsm_x4(uint32_t* r, uint32_t addr) {
    asm volatile("ldmatrix.sync.aligned.m8n8.x4.shared.b16 {%0,%1,%2,%3}, [%4];"
                 : "=r"(r[0]), "=r"(r[1]), "=r"(r[2]), "=r"(r[3]) : "r"(addr));
}
__device__ __forceinline__ void mma_f16(float* c, const uint32_t* a, uint32_t b0, uint32_t b1) {
    asm volatile("mma.sync.aligned.m16n8k16.row.col.f32.f16.f16.f32 "
                 "{%0,%1,%2,%3}, {%4,%5,%6,%7}, {%8,%9}, {%0,%1,%2,%3};"
                 : "+f"(c[0]), "+f"(c[1]), "+f"(c[2]), "+f"(c[3])
                 : "r"(a[0]), "r"(a[1]), "r"(a[2]), "r"(a[3]), "r"(b0), "r"(b1));
}
__device__ __forceinline__ uint32_t sw_addr(uint32_t base, int row, int chunk) {
    return base + (uint32_t)(((row << 3) + (chunk ^ (row & 7))) << 4);
}

// ---------------- epilogue modes ----------------
#define EPI_NONE        0
#define EPI_SCORES_H    1
#define EPI_RES         2
#define EPI_RES_GATE    3
#define EPI_H           4
#define EPI_GELUMUL_HH  5
#define EPI_QKV         6

// ---------------- TC fp16 GEMM: C[M,N] = A[M,Kp] * Bt[N,Kp]^T ----------------
struct TcP {
    const __half* A; const __half* Bt;
    float* C; __half* Ch;
    float* Ck; float* Cv;
    const float* aux; const __half* auxh; const float* gvec;
    const int *cs, *pad;
    size_t zA1, zA2, zB1, zB2, zC1, zC2, zAux, zGv;
    int zdiv;
    int gstride, gdiv;
    int maskStride; float scale;
    int M, N, Kp, epi;
    int rpb, obatch, ldc;
};

#define TC_STAGES 3
#define TC_STAGE_BYTES 32768
#define TC_SMEM (TC_STAGES * TC_STAGE_BYTES)

__global__ __launch_bounds__(256) void tc_gemm_kernel(TcP p) {
    extern __shared__ char dsm[];
    uint32_t sbase = smem_u32(dsm);

    int tid  = threadIdx.x;
    int wid  = tid >> 5;
    int lane = tid & 31;
    int wm = wid >> 2;
    int wn = wid & 3;

    int m0 = blockIdx.y * 128;
    int n0 = blockIdx.x * 128;
    int z  = blockIdx.z;
    int zb = z / p.zdiv;
    int zr = z - zb * p.zdiv;

    const __half* Ab = p.A  + (size_t)zb * p.zA1 + (size_t)zr * p.zA2;
    const __half* Bb = p.Bt + (size_t)zb * p.zB1 + (size_t)zr * p.zB2;

    int kc = tid & 7;
    int rb = tid >> 3;

    float acc[4][4][4];
    #pragma unroll
    for (int i = 0; i < 4; i++)
        #pragma unroll
        for (int j = 0; j < 4; j++)
            #pragma unroll
            for (int e = 0; e < 4; e++) acc[i][j][e] = 0.f;

    int nIter = p.Kp >> 6;

    auto issue = [&](int it) {
        int st = it % TC_STAGES;
        uint32_t sa = sbase + st * TC_STAGE_BYTES;
        uint32_t sb = sa + 16384;
        int k0 = it << 6;
        #pragma unroll
        for (int i = 0; i < 4; i++) {
            int row = rb + i * 32;
            int ra = m0 + row; if (ra > p.M - 1) ra = p.M - 1;
            CP_ASYNC16(sw_addr(sa, row, kc), Ab + (size_t)ra * p.Kp + k0 + kc * 8);
            int rn = n0 + row; if (rn > p.N - 1) rn = p.N - 1;
            CP_ASYNC16(sw_addr(sb, row, kc), Bb + (size_t)rn * p.Kp + k0 + kc * 8);
        }
        CP_COMMIT();
    };

    #pragma unroll
    for (int s = 0; s < TC_STAGES - 1; s++) issue(s);

    int grp = lane >> 3;
    int lr  = lane & 7;

    for (int it = 0; it < nIter; it++) {
        if (it + TC_STAGES - 1 < nIter) {
            issue(it + TC_STAGES - 1);
            CP_WAIT(TC_STAGES - 2);
        } else {
            CP_WAIT(0);
        }
        __syncthreads();

        int st = it % TC_STAGES;
        uint32_t sa = sbase + st * TC_STAGE_BYTES;
        uint32_t sb = sa + 16384;

        #pragma unroll
        for (int kb = 0; kb < 4; kb++) {
            int chA = 2 * kb + (grp >> 1);
            uint32_t a[4][4];
            #pragma unroll
            for (int mi = 0; mi < 4; mi++) {
                int row = wm * 64 + mi * 16 + (grp & 1) * 8 + lr;
                ldsm_x4(a[mi], sw_addr(sa, row, chA));
            }
            uint32_t bf[2][4];
            #pragma unroll
            for (int bi = 0; bi < 2; bi++) {
                int row = wn * 32 + bi * 16 + (grp & 1) * 8 + lr;
                ldsm_x4(bf[bi], sw_addr(sb, row, chA));
            }
            #pragma unroll
            for (int mi = 0; mi < 4; mi++)
                #pragma unroll
                for (int ni = 0; ni < 4; ni++) {
                    int bi = ni >> 1, wh = ni & 1;
                    mma_f16(acc[mi][ni], a[mi], bf[bi][wh], bf[bi][wh + 2]);
                }
        }
        __syncthreads();
    }

    // ---- epilogue ----
    const int* csb  = p.cs  ? p.cs  + (size_t)zb * p.maskStride : nullptr;
    const int* padb = p.pad ? p.pad + (size_t)zb * p.maskStride : nullptr;
    const float* auxz = p.aux ? p.aux + (size_t)zb * p.zAux : nullptr;
    const __half* auxhz = p.auxh ? p.auxh + (size_t)zb * p.zAux : nullptr;
    const float* gvz  = p.gvec ? p.gvec + (size_t)zb * p.zGv : nullptr;
    float* Cz = p.C + (size_t)zb * p.zC1 + (size_t)zr * p.zC2;
    __half* Chz = p.Ch + (size_t)zb * p.zC1 + (size_t)zr * p.zC2;
    int qrow = lane >> 2;
    int qcol = (lane & 3) * 2;
    #pragma unroll
    for (int mi = 0; mi < 4; mi++) {
        #pragma unroll
        for (int half_ = 0; half_ < 2; half_++) {
            int r = m0 + wm * 64 + mi * 16 + half_ * 8 + qrow;
            if (r >= p.M) continue;
            int orow = (r / p.rpb) * p.obatch + (r % p.rpb);
            #pragma unroll
            for (int ni = 0; ni < 4; ni++) {
                int col = n0 + wn * 32 + ni * 8 + qcol;
                if (col >= p.N) continue;
                float v0 = acc[mi][ni][half_ * 2 + 0];
                float v1 = acc[mi][ni][half_ * 2 + 1];
                if (p.epi == EPI_QKV) {
                    float2 ov = make_float2(v0, v1);
                    if (col < H_ * HD_)
                        *(float2*)&p.C[(size_t)orow * (H_ * HD_) + col] = ov;
                    else if (col < H_ * HD_ + HD_)
                        *(float2*)&p.Ck[(size_t)orow * HD_ + (col - H_ * HD_)] = ov;
                    else
                        *(float2*)&p.Cv[(size_t)orow * HD_ + (col - H_ * HD_ - HD_)] = ov;
                    continue;
                } else if (p.epi == EPI_H) {
                    __half2 hv; hv.x = __float2half(v0); hv.y = __float2half(v1);
                    *(__half2*)&Chz[(size_t)orow * p.ldc + col] = hv;
                    continue;
                } else if (p.epi == EPI_GELUMUL_HH) {
                    __half2 ah = *(const __half2*)&auxhz[(size_t)r * p.N + col];
                    __half2 hv;
                    hv.x = __float2half(gelu_tanh(__half2float(ah.x)) * v0);
                    hv.y = __float2half(gelu_tanh(__half2float(ah.y)) * v1);
                    *(__half2*)&Chz[(size_t)orow * p.ldc + col] = hv;
                    continue;
                } else if (p.epi == EPI_SCORES_H) {
                    int csr = csb[r];
                    bool okr = padb[r] != 0;
                    bool ok0 = (csb[col] <= csr) && okr && (padb[col] != 0);
                    bool ok1 = (csb[col + 1] <= csr) && okr && (padb[col + 1] != 0);
                    __half2 hv;
                    hv.x = __float2half(ok0 ? v0 * p.scale : MASK_H_);
                    hv.y = __float2half(ok1 ? v1 * p.scale : MASK_H_);
                    *(__half2*)&Chz[(size_t)orow * p.ldc + col] = hv;
                    continue;
                } else if (p.epi == EPI_RES) {
                    float2 ax = *(const float2*)&auxz[(size_t)r * p.N + col];
                    v0 += ax.x; v1 += ax.y;
                } else if (p.epi == EPI_RES_GATE) {
                    float2 ax = *(const float2*)&auxz[(size_t)r * p.N + col];
                    float2 gx = *(const float2*)&gvz[(size_t)(r / p.gdiv) * p.gstride + col];
                    v0 = ax.x + gx.x * v0;
                    v1 = ax.y + gx.y * v1;
                }
                *(float2*)&Cz[(size_t)orow * p.ldc + col] = make_float2(v0, v1);
            }
        }
    }
}

// ---------------- multi-weight transpose fp32 -> fp16 ----------------
#define WT_MAX 8
struct WtEntry { const float* src; __half* dst; int K, N, nx, blkOff; };
struct WtP { WtEntry e[WT_MAX]; int cnt; };

__global__ void wtrans_multi_kernel(WtP p) {
    int bx = blockIdx.x;
    int i = p.cnt - 1;
    while (i > 0 && bx < p.e[i].blkOff) i--;
    WtEntry e = p.e[i];
    int local = bx - e.blkOff;
    int n0 = (local % e.nx) * 32;
    int k0 = (local / e.nx) * 64;

    __shared__ float t[64][33];
    int tx = threadIdx.x, ty = threadIdx.y;
    #pragma unroll
    for (int j = 0; j < 8; j++)
        t[ty + j * 8][tx] = e.src[(size_t)(k0 + ty + j * 8) * e.N + n0 + tx];
    __syncthreads();
    #pragma unroll
    for (int j = 0; j < 4; j++) {
        int nl = j * 8 + ty;
        __half2 hv;
        hv.x = __float2half(t[2 * tx][nl]);
        hv.y = __float2half(t[2 * tx + 1][nl]);
        *(__half2*)&e.dst[(size_t)(n0 + nl) * e.K + k0 + 2 * tx] = hv;
    }
}

// batched V transpose (z over B)
__global__ void wtrans_kernel(const float* __restrict__ W, __half* __restrict__ out,
                              int K, int N, size_t inZ, size_t outZ) {
    W   += blockIdx.z * inZ;
    out += blockIdx.z * outZ;
    __shared__ float t[64][33];
    int k0 = blockIdx.y * 64, n0 = blockIdx.x * 32;
    int tx = threadIdx.x, ty = threadIdx.y;
    #pragma unroll
    for (int i = 0; i < 8; i++)
        t[ty + i * 8][tx] = W[(size_t)(k0 + ty + i * 8) * N + n0 + tx];
    __syncthreads();
    #pragma unroll
    for (int j = 0; j < 4; j++) {
        int nl = j * 8 + ty;
        __half2 hv;
        hv.x = __float2half(t[2 * tx][nl]);
        hv.y = __float2half(t[2 * tx + 1][nl]);
        *(__half2*)&out[(size_t)(n0 + nl) * K + k0 + 2 * tx] = hv;
    }
}

// merged RoPE (Q then K ranges) -> fp16
__global__ void rope_qk_kernel(const float* __restrict__ q, const float* __restrict__ k,
                               const int* __restrict__ pos,
                               __half* __restrict__ qr, __half* __restrict__ kr) {
    const long NQ = (long)B_ * H_ * S_ * 128;
    const long NK = (long)B_ * S_ * 128;
    long idx = blockIdx.x * (long)blockDim.x + threadIdx.x;
    if (idx >= NQ + NK) return;
    if (idx < NQ) {
        int i = (int)(idx & 127);
        long t = idx >> 7;
        int s = (int)(t % S_); t /= S_;
        int h = (int)(t % H_);
        int b = (int)(t / H_);
        const float* base = q + ((size_t)(b * S_ + s) * H_ + h) * HD_;
        float x1 = base[i], x2 = base[i + 128];
        float f = (float)pos[b * S_ + s] * expf(-((float)i / 128.0f) * 9.210340371976184f);
        float sn, c; sincosf(f, &sn, &c);
        __half* ob = qr + ((size_t)(b * H_ + h) * S_ + s) * HD_;
        ob[i]       = __float2half(x1 * c - x2 * sn);
        ob[i + 128] = __float2half(x2 * c + x1 * sn);
    } else {
        idx -= NQ;
        int i = (int)(idx & 127);
        long t = idx >> 7;
        int s = (int)(t % S_);
        int b = (int)(t / S_);
        const float* base = k + (size_t)(b * S_ + s) * HD_;
        float x1 = base[i], x2 = base[i + 128];
        float f = (float)pos[b * S_ + s] * expf(-((float)i / 128.0f) * 9.210340371976184f);
        float sn, c; sincosf(f, &sn, &c);
        __half* ob = kr + (size_t)(b * S_ + s) * HD_;
        ob[i]       = __float2half(x1 * c - x2 * sn);
        ob[i + 128] = __float2half(x2 * c + x1 * sn);
    }
}

// elementwise gelu-mul (stream-1 fused gate|up)
__global__ void ew_gelumul_kernel(const __half* __restrict__ gu, __half* __restrict__ out,
                                  int M, int F) {
    long idx = blockIdx.x * (long)blockDim.x + threadIdx.x;
    if (idx >= (long)M * F) return;
    int r = (int)(idx / F), j = (int)(idx % F);
    const __half* g = gu + (size_t)r * 2 * F;
    out[(size_t)r * F + j] =
        __float2half(gelu_tanh(__half2float(g[j])) * __half2float(g[F + j]));
}

// merged mod GEMV
__global__ void mod2_kernel(const float* __restrict__ cond,
                            const float* __restrict__ W0, const float* __restrict__ b0, float* __restrict__ o0,
                            const float* __restrict__ W1, const float* __restrict__ b1, float* __restrict__ o1,
                            int D, int N) {
    const float* W = blockIdx.z ? W1 : W0;
    const float* bias = blockIdx.z ? b1 : b0;
    float* out = blockIdx.z ? o1 : o0;
    __shared__ float red[256];
    int tid = threadIdx.x;
    int j = blockIdx.x * 64 + (tid & 63);
    int ks = tid >> 6;
    int b = blockIdx.y;
    const float* c = cond + (size_t)b * D;
    int kseg = D >> 2;
    int kbeg = ks * kseg;
    float s = 0.f;
    for (int kk = kbeg; kk < kbeg + kseg; kk++)
        s += c[kk] * W[(size_t)kk * N + j];
    red[tid] = s;
    __syncthreads();
    if (ks == 0)
        out[(size_t)b * N + j] = bias[j] + red[tid] + red[tid + 64] + red[tid + 128] + red[tid + 192];
}

// parallel prefix scan (block per batch)
__global__ void scan_par_kernel(const int* __restrict__ pad, const int* __restrict__ att,
                                int* __restrict__ pos, int* __restrict__ cs) {
    __shared__ int sp[1024];
    __shared__ int sa[1024];
    int b = blockIdx.x;
    int t = threadIdx.x;
    int vp = 0, va = 0;
    if (t < S_) {
        vp = pad[b * S_ + t];
        va = att[b * S_ + t];
    }
    sp[t] = vp; sa[t] = va;
    __syncthreads();
    #pragma unroll
    for (int off = 1; off < 1024; off <<= 1) {
        int ap = 0, aa = 0;
        if (t >= off) { ap = sp[t - off]; aa = sa[t - off]; }
        __syncthreads();
        sp[t] += ap; sa[t] += aa;
        __syncthreads();
    }
    if (t < S_) {
        pos[b * S_ + t] = sp[t] - 1;
        cs[b * S_ + t] = sa[t];
    }
}

// merged RMSNorm (two tensors, row-routed) -> fp16
__global__ void rmsnorm2_kernel(const float* __restrict__ xA, __half* __restrict__ oA,
                                const float* __restrict__ wA, int wsA, int DA, int rpbA, int MA,
                                const float* __restrict__ xB, __half* __restrict__ oB,
                                const float* __restrict__ wB, int wsB, int DB, int rpbB) {
    long row = blockIdx.x;
    const float* xp; __half* op; const float* wp; int D;
    if (row < MA) {
        xp = xA + row * (long)DA; op = oA + row * (long)DA;
        wp = wA + (size_t)(row / rpbA) * wsA; D = DA;
    } else {
        long r2 = row - MA;
        xp = xB + r2 * (long)DB; op = oB + r2 * (long)DB;
        wp = wB + (size_t)(r2 / rpbB) * wsB; D = DB;
    }
    float ss = 0.f;
    for (int i = threadIdx.x; i < D; i += blockDim.x) {
        float v = xp[i];
        ss += v * v;
    }
    __shared__ float red[256];
    red[threadIdx.x] = ss;
    __syncthreads();
    for (int s = 128; s > 0; s >>= 1) {
        if (threadIdx.x < s) red[threadIdx.x] += red[threadIdx.x + s];
        __syncthreads();
    }
    float r = rsqrtf(red[0] / (float)D + EPS_);
    for (int i = threadIdx.x; i < D; i += blockDim.x)
        op[i] = __float2half(xp[i] * r * (1.0f + wp[i]));
}

// row softmax on fp16 in-place
__global__ void softmax_h_kernel(__half* __restrict__ probs) {
    __half* p = probs + (size_t)blockIdx.x * S_;
    __shared__ float red[256];
    int tid = threadIdx.x;
    float loc[4];
    float m = -3.4e38f;
    for (int c = 0, i = tid; i < S_; i += 256, c++) {
        loc[c] = __half2float(p[i]);
        m = fmaxf(m, loc[c]);
    }
    red[tid] = m;
    __syncthreads();
    for (int s = 128; s > 0; s >>= 1) {
        if (tid < s) red[tid] = fmaxf(red[tid], red[tid + s]);
        __syncthreads();
    }
    m = red[0];
    __syncthreads();
    float sum = 0.f;
    for (int c = 0, i = tid; i < S_; i += 256, c++) {
        float e = expf(loc[c] - m);
        loc[c] = e;
        sum += e;
    }
    red[tid] = sum;
    __syncthreads();
    for (int s = 128; s > 0; s >>= 1) {
        if (tid < s) red[tid] += red[tid + s];
        __syncthreads();
    }
    float inv = 1.0f / red[0];
    for (int c = 0, i = tid; i < S_; i += 256, c++)
        p[i] = __float2half(loc[c] * inv);
}

// ---------------- host helper ----------------
struct TcArgs {
    const __half* A; const __half* Bt;
    float* C; __half* Ch = nullptr;
    int M = 0, N = 0, Kp = 0, epi = 0;
    const float* aux = nullptr;
    int rpb = 0, obatch = 0, ldc = 0;
    int zcount = 1, zdiv = 1;
    size_t zA1 = 0, zA2 = 0, zB1 = 0, zB2 = 0, zC1 = 0, zC2 = 0, zAux = 0, zGv = 0;
    const int* cs = nullptr; const int* pad = nullptr;
    int maskStride = 0; float scale = 1.0f;
    const float* gvec = nullptr; int gstride = 0, gdiv = 1;
    float* Ck = nullptr; float* Cv = nullptr;
    const __half* auxh = nullptr;
    cudaStream_t st = 0;
};

static void launch_tc(const TcArgs& a) {
    cudaFuncSetAttribute(tc_gemm_kernel, cudaFuncAttributeMaxDynamicSharedMemorySize, TC_SMEM);
    TcP p;
    p.A = a.A; p.Bt = a.Bt; p.C = a.C; p.Ch = a.Ch; p.Ck = a.Ck; p.Cv = a.Cv;
    p.aux = a.aux; p.auxh = a.auxh; p.gvec = a.gvec;
    p.cs = a.cs; p.pad = a.pad;
    p.zA1 = a.zA1; p.zA2 = a.zA2; p.zB1 = a.zB1; p.zB2 = a.zB2;
    p.zC1 = a.zC1; p.zC2 = a.zC2; p.zAux = a.zAux; p.zGv = a.zGv;
    p.zdiv = a.zdiv; p.gstride = a.gstride; p.gdiv = a.gdiv;
    p.maskStride = a.maskStride; p.scale = a.scale;
    p.M = a.M; p.N = a.N; p.Kp = a.Kp; p.epi = a.epi;
    p.rpb = a.rpb ? a.rpb : a.M; p.obatch = a.obatch; p.ldc = a.ldc ? a.ldc : a.N;
    dim3 grid((a.N + 127) / 128, (a.M + 127) / 128, a.zcount);
    tc_gemm_kernel<<<grid, 256, TC_SMEM, a.st>>>(p);
}

struct WtBuild {
    WtP p;
    int total = 0;
    WtBuild() { p.cnt = 0; }
    void add(const float* src, __half* dst, int K, int N) {
        WtEntry& e = p.e[p.cnt++];
        e.src = src; e.dst = dst; e.K = K; e.N = N;
        e.nx = N / 32;
        e.blkOff = total;
        total += (N / 32) * (K / 64);
    }
    void launch(cudaStream_t st) {
        wtrans_multi_kernel<<<total, dim3(32, 8), 0, st>>>(p);
    }
};

extern "C" void kernel_launch(void* const* d_in, const int* in_sizes, int n_in,
                              void* d_out, int out_size) {
    const float* x0         = (const float*)d_in[0];
    const float* x1         = (const float*)d_in[1];
    const float* cond1      = (const float*)d_in[2];
    const float* w_q0       = (const float*)d_in[3];
    const float* w_k0       = (const float*)d_in[4];
    const float* w_v0       = (const float*)d_in[5];
    const float* w_o0       = (const float*)d_in[6];
    const float* norm1_w0   = (const float*)d_in[7];
    const float* norm2_w0   = (const float*)d_in[8];
    const float* w_gate0    = (const float*)d_in[9];
    const float* w_up0      = (const float*)d_in[10];
    const float* w_down0    = (const float*)d_in[11];
    const float* w_q1       = (const float*)d_in[12];
    const float* w_k1       = (const float*)d_in[13];
    const float* w_v1       = (const float*)d_in[14];
    const float* w_o1       = (const float*)d_in[15];
    const float* ada_in_w1  = (const float*)d_in[16];
    const float* ada_in_b1  = (const float*)d_in[17];
    const float* ada_post_w1= (const float*)d_in[18];
    const float* ada_post_b1= (const float*)d_in[19];
    const float* w_gate1    = (const float*)d_in[20];
    const float* w_up1      = (const float*)d_in[21];
    const float* w_down1    = (const float*)d_in[22];
    const int*   pad_masks  = (const int*)d_in[23];
    const int*   att_masks  = (const int*)d_in[24];

    float* out0 = (float*)d_out;
    float* out1 = out0 + (size_t)B_ * S1_ * D0_;

    float *modin, *modpost, *q, *k, *v, *r0, *r1;
    int *pos, *cs;
    __half *hc0, *hc1, *qr, *kr, *vt, *ph, *atth, *yc0, *yc1;
    __half *gu0hg, *gu0h, *gu1h2, *gu1h;
    __half *wqkv0t, *wqkv1t, *wo0t, *wg0t, *wu0t, *wd0t, *wo1t, *wgu1t, *wd1t;
    cudaGetSymbolAddress((void**)&modin, g_mod_in);
    cudaGetSymbolAddress((void**)&modpost, g_mod_post);
    cudaGetSymbolAddress((void**)&q, g_q);
    cudaGetSymbolAddress((void**)&k, g_k);
    cudaGetSymbolAddress((void**)&v, g_v);
    cudaGetSymbolAddress((void**)&r0, g_r0);
    cudaGetSymbolAddress((void**)&r1, g_r1);
    cudaGetSymbolAddress((void**)&pos, g_pos);
    cudaGetSymbolAddress((void**)&cs, g_cs);
    cudaGetSymbolAddress((void**)&hc0, g_hc0);
    cudaGetSymbolAddress((void**)&hc1, g_hc1);
    cudaGetSymbolAddress((void**)&qr, g_qr);
    cudaGetSymbolAddress((void**)&kr, g_kr);
    cudaGetSymbolAddress((void**)&vt, g_vt);
    cudaGetSymbolAddress((void**)&ph, g_ph);
    cudaGetSymbolAddress((void**)&atth, g_atth);
    cudaGetSymbolAddress((void**)&yc0, g_yc0);
    cudaGetSymbolAddress((void**)&yc1, g_yc1);
    cudaGetSymbolAddress((void**)&gu0hg, g_gu0hg);
    cudaGetSymbolAddress((void**)&gu0h, g_gu0h);
    cudaGetSymbolAddress((void**)&gu1h2, g_gu1h2);
    cudaGetSymbolAddress((void**)&gu1h, g_gu1h);
    cudaGetSymbolAddress((void**)&wqkv0t, g_wqkv0t);
    cudaGetSymbolAddress((void**)&wqkv1t, g_wqkv1t);
    cudaGetSymbolAddress((void**)&wo0t, g_wo0t);
    cudaGetSymbolAddress((void**)&wg0t, g_wg0t);
    cudaGetSymbolAddress((void**)&wu0t, g_wu0t);
    cudaGetSymbolAddress((void**)&wd0t, g_wd0t);
    cudaGetSymbolAddress((void**)&wo1t, g_wo1t);
    cudaGetSymbolAddress((void**)&wgu1t, g_wgu1t);
    cudaGetSymbolAddress((void**)&wd1t, g_wd1t);

    const int M0 = B_ * S1_;   // 3072
    const int M1 = B_ * S2_;   // 256

    // ---- side stream + events (created once, outside capture) ----
    static cudaStream_t s2 = nullptr;
    static cudaEvent_t evFork = nullptr, evJoin = nullptr, evAtth = nullptr, evDone1 = nullptr;
    if (!s2) {
        cudaStreamCreate(&s2);
        cudaEventCreateWithFlags(&evFork, cudaEventDisableTiming);
        cudaEventCreateWithFlags(&evJoin, cudaEventDisableTiming);
        cudaEventCreateWithFlags(&evAtth, cudaEventDisableTiming);
        cudaEventCreateWithFlags(&evDone1, cudaEventDisableTiming);
    }

    // fork: merged conversion of late-consumed weights on side stream
    cudaEventRecord(evFork, 0);
    cudaStreamWaitEvent(s2, evFork, 0);
    {
        WtBuild wb;
        wb.add(w_o0,    wo0t, H_ * HD_, D0_);
        wb.add(w_gate0, wg0t, D0_, F0_);
        wb.add(w_up0,   wu0t, D0_, F0_);
        wb.add(w_down0, wd0t, F0_, D0_);
        wb.add(w_o1,    wo1t, H_ * HD_, D1_);
        wb.add(w_gate1, wgu1t, D1_, F1_);
        wb.add(w_up1,   wgu1t + (size_t)F1_ * D1_, D1_, F1_);
        wb.add(w_down1, wd1t, F1_, D1_);
        wb.launch(s2);
    }
    cudaEventRecord(evJoin, s2);

    // main stream: merged QKV weight conversion
    {
        WtBuild wb;
        wb.add(w_q0, wqkv0t, D0_, H_ * HD_);
        wb.add(w_k0, wqkv0t + (size_t)(H_ * HD_) * D0_, D0_, HD_);
        wb.add(w_v0, wqkv0t + (size_t)(H_ * HD_ + HD_) * D0_, D0_, HD_);
        wb.add(w_q1, wqkv1t, D1_, H_ * HD_);
        wb.add(w_k1, wqkv1t + (size_t)(H_ * HD_) * D1_, D1_, HD_);
        wb.add(w_v1, wqkv1t + (size_t)(H_ * HD_ + HD_) * D1_, D1_, HD_);
        wb.launch(0);
    }

    // ---- adaLN modulation (merged) + parallel scans ----
    {
        dim3 mg(2 * D1_ / 64, B_, 2);
        mod2_kernel<<<mg, 256>>>(cond1, ada_in_w1, ada_in_b1, modin,
                                 ada_post_w1, ada_post_b1, modpost, D1_, 2 * D1_);
    }
    scan_par_kernel<<<B_, 1024>>>(pad_masks, att_masks, pos, cs);

    // ---- input norms (merged) -> fp16 ----
    rmsnorm2_kernel<<<M0 + M1, 256>>>(x0, hc0, norm1_w0, 0, D0_, S1_, M0,
                                      x1, hc1, modin, 2 * D1_, D1_, S2_);

    // ---- fused QKV projections ----
    { TcArgs a{hc0, wqkv0t, q, nullptr, M0, NQKV_, D0_, EPI_QKV};
      a.Ck = k; a.Cv = v;
      a.rpb = S1_; a.obatch = S_; launch_tc(a); }
    { TcArgs a{hc1, wqkv1t, q + (size_t)S1_ * H_ * HD_, nullptr, M1, NQKV_, D1_, EPI_QKV};
      a.Ck = k + (size_t)S1_ * HD_; a.Cv = v + (size_t)S1_ * HD_;
      a.rpb = S2_; a.obatch = S_; launch_tc(a); }

    // ---- merged RoPE + V transpose ----
    {
        long ntot = (long)B_ * H_ * S_ * 128 + (long)B_ * S_ * 128;
        rope_qk_kernel<<<(unsigned)((ntot + 255) / 256), 256>>>(q, k, pos, qr, kr);
        dim3 vg(HD_ / 32, S_ / 64, B_);
        wtrans_kernel<<<vg, dim3(32, 8)>>>(v, vt, S_, HD_, (size_t)S_ * HD_, (size_t)HD_ * S_);
    }

    // ---- scores = Q K^T * scale, masked -> fp16 ph (z = B*H) ----
    { TcArgs a{qr, kr, nullptr, ph, S_, S_, HD_, EPI_SCORES_H};
      a.zcount = B_ * H_; a.zdiv = H_;
      a.zA1 = (size_t)H_ * S_ * HD_; a.zA2 = (size_t)S_ * HD_;
      a.zB1 = (size_t)S_ * HD_;
      a.zC1 = (size_t)H_ * S_ * S_; a.zC2 = (size_t)S_ * S_;
      a.cs = cs; a.pad = pad_masks; a.maskStride = S_; a.scale = 0.0625f;
      launch_tc(a); }

    softmax_h_kernel<<<B_ * H_ * S_, 256>>>(ph);

    // ---- PV (z = B*H) -> atth fp16 ----
    { TcArgs a{ph, vt, nullptr, atth, S_, HD_, S_, EPI_H};
      a.ldc = H_ * HD_;
      a.zcount = B_ * H_; a.zdiv = H_;
      a.zA1 = (size_t)H_ * S_ * S_; a.zA2 = (size_t)S_ * S_;
      a.zB1 = (size_t)HD_ * S_;
      a.zC1 = (size_t)S_ * H_ * HD_; a.zC2 = (size_t)HD_;
      launch_tc(a); }
    cudaEventRecord(evAtth, 0);

    // ======== SIDE STREAM: entire stream-1 chain (fills stream-0 tail waves) ========
    cudaStreamWaitEvent(s2, evAtth, 0);
    { TcArgs a{atth + (size_t)S1_ * H_ * HD_, wo1t, r1, nullptr, S2_, D1_, H_ * HD_, EPI_RES_GATE};
      a.aux = x1;
      a.zcount = B_;
      a.zA1 = (size_t)S_ * H_ * HD_; a.zC1 = (size_t)S2_ * D1_; a.zAux = (size_t)S2_ * D1_;
      a.gvec = modin + D1_; a.zGv = (size_t)2 * D1_; a.gdiv = S2_; a.gstride = 0;
      a.st = s2; launch_tc(a); }
    // stream-1 post norm only (MA=0 routes all rows to B side)
    rmsnorm2_kernel<<<M1, 256, 0, s2>>>(nullptr, nullptr, nullptr, 0, 1, 1, 0,
                                        r1, yc1, modpost, 2 * D1_, D1_, S2_);
    { TcArgs a{yc1, wgu1t, nullptr, gu1h2, M1, 2 * F1_, D1_, EPI_H}; a.st = s2; launch_tc(a); }
    {
        long n = (long)M1 * F1_;
        ew_gelumul_kernel<<<(unsigned)((n + 255) / 256), 256, 0, s2>>>(gu1h2, gu1h, M1, F1_);
    }
    { TcArgs a{gu1h, wd1t, out1, nullptr, M1, D1_, F1_, EPI_RES_GATE};
      a.aux = r1;
      a.gvec = modpost + D1_; a.gstride = 2 * D1_; a.gdiv = S2_;
      a.st = s2; launch_tc(a); }
    cudaEventRecord(evDone1, s2);

    // ======== MAIN STREAM: stream-0 chain ========
    // join: side-stream weight conversions before o0 / MLP0
    cudaStreamWaitEvent(0, evJoin, 0);

    { TcArgs a{atth, wo0t, r0, nullptr, S1_, D0_, H_ * HD_, EPI_RES};
      a.aux = x0;
      a.zcount = B_;
      a.zA1 = (size_t)S_ * H_ * HD_; a.zC1 = (size_t)S1_ * D0_; a.zAux = (size_t)S1_ * D0_;
      launch_tc(a); }

    // stream-0 post norm only
    rmsnorm2_kernel<<<M0, 256>>>(r0, yc0, norm2_w0, 0, D0_, S1_, M0,
                                 nullptr, nullptr, nullptr, 0, 1, 1);

    { TcArgs a{yc0, wg0t, nullptr, gu0hg, M0, F0_, D0_, EPI_H}; launch_tc(a); }
    { TcArgs a{yc0, wu0t, nullptr, gu0h, M0, F0_, D0_, EPI_GELUMUL_HH}; a.auxh = gu0hg; launch_tc(a); }
    { TcArgs a{gu0h, wd0t, out0, nullptr, M0, D0_, F0_, EPI_RES}; a.aux = r0; launch_tc(a); }

    // final join: stream-1 chain must complete before harness reads d_out
    cudaStreamWaitEvent(0, evDone1, 0);
}

// round 17
// speedup vs baseline: 1.0943x; 1.0183x over previous
#include <cuda_runtime.h>
#include <cuda_fp16.h>
#include <math.h>
#include <stdint.h>

// ---------------- problem constants ----------------
#define B_   4
#define S1_  768
#define S2_  64
#define S_   832
#define D0_  2048
#define F0_  16384
#define D1_  1024
#define F1_  4096
#define H_   8
#define HD_  256
#define EPS_ 1e-6f
#define MASK_H_  -60000.0f
#define NQKV_ (H_*HD_ + 2*HD_)   // 2560

// ---------------- scratch (device globals) ----------------
__device__ float g_mod_in[B_*2*D1_];
__device__ float g_mod_post[B_*2*D1_];
__device__ float g_q[(size_t)B_*S_*H_*HD_];
__device__ float g_k[B_*S_*HD_];
__device__ float g_v[B_*S_*HD_];
__device__ float g_r0[B_*S1_*D0_];
__device__ float g_r1[B_*S2_*D1_];
__device__ int   g_pos[B_*S_];
__device__ int   g_cs[B_*S_];
// fp16 operands
__device__ __half g_hc0[(size_t)B_*S1_*D0_];
__device__ __half g_hc1[B_*S2_*D1_];
__device__ __half g_qr[(size_t)B_*H_*S_*HD_];
__device__ __half g_kr[B_*S_*HD_];
__device__ __half g_vt[B_*HD_*S_];
__device__ __half g_ph[(size_t)B_*H_*S_*S_];
__device__ __half g_atth[(size_t)B_*S_*H_*HD_];
__device__ __half g_yc0[(size_t)B_*S1_*D0_];
__device__ __half g_yc1[B_*S2_*D1_];
__device__ __half g_gu0hg[(size_t)B_*S1_*F0_];
__device__ __half g_gu0h[(size_t)B_*S1_*F0_];
__device__ __half g_gu1h2[(size_t)B_*S2_*2*F1_];
__device__ __half g_gu1h[B_*S2_*F1_];
// transposed fp16 weights [N, K]
__device__ __half g_wqkv0t[(size_t)NQKV_*2048];
__device__ __half g_wqkv1t[(size_t)NQKV_*1024];
__device__ __half g_wo0t[(size_t)2048*2048];
__device__ __half g_wg0t[(size_t)16384*2048];
__device__ __half g_wu0t[(size_t)16384*2048];
__device__ __half g_wd0t[(size_t)2048*16384];
__device__ __half g_wo1t[(size_t)1024*2048];
__device__ __half g_wgu1t[(size_t)2*4096*1024];
__device__ __half g_wd1t[(size_t)1024*4096];

// ---------------- helpers ----------------
__device__ __forceinline__ float gelu_tanh(float x) {
    float x3 = x * x * x;
    return 0.5f * x * (1.0f + tanhf(0.79788456080286535588f * (x + 0.044715f * x3)));
}
__device__ __forceinline__ uint32_t smem_u32(const void* p) {
    uint32_t a;
    asm("{ .reg .u64 t; cvta.to.shared.u64 t, %1; cvt.u32.u64 %0, t; }" : "=r"(a) : "l"(p));
    return a;
}
#define CP_ASYNC16(sm, gm) \
    asm volatile("cp.async.cg.shared.global [%0], [%1], 16;" :: "r"(sm), "l"(gm))
#define CP_COMMIT() asm volatile("cp.async.commit_group;")
#define CP_WAIT(n)  asm volatile("cp.async.wait_group %0;" :: "n"(n))

__device__ __forceinline__ void ldsm_x4(uint32_t* r, uint32_t addr) {
    asm volatile("ldmatrix.sync.aligned.m8n8.x4.shared.b16 {%0,%1,%2,%3}, [%4];"
                 : "=r"(r[0]), "=r"(r[1]), "=r"(r[2]), "=r"(r[3]) : "r"(addr));
}
__device__ __forceinline__ void mma_f16(float* c, const uint32_t* a, uint32_t b0, uint32_t b1) {
    asm volatile("mma.sync.aligned.m16n8k16.row.col.f32.f16.f16.f32 "
                 "{%0,%1,%2,%3}, {%4,%5,%6,%7}, {%8,%9}, {%0,%1,%2,%3};"
                 : "+f"(c[0]), "+f"(c[1]), "+f"(c[2]), "+f"(c[3])
                 : "r"(a[0]), "r"(a[1]), "r"(a[2]), "r"(a[3]), "r"(b0), "r"(b1));
}
__device__ __forceinline__ uint32_t sw_addr(uint32_t base, int row, int chunk) {
    return base + (uint32_t)(((row << 3) + (chunk ^ (row & 7))) << 4);
}

// ---------------- epilogue modes ----------------
#define EPI_NONE        0
#define EPI_SCORES_H    1
#define EPI_RES         2
#define EPI_RES_GATE    3
#define EPI_H           4
#define EPI_GELUMUL_HH  5
#define EPI_QKV         6

// ---------------- TC fp16 GEMM: C[M,N] = A[M,Kp] * Bt[N,Kp]^T ----------------
struct TcP {
    const __half* A; const __half* Bt;
    float* C; __half* Ch;
    float* Ck; float* Cv;
    const float* aux; const __half* auxh; const float* gvec;
    const int *cs, *pad;
    size_t zA1, zA2, zB1, zB2, zC1, zC2, zAux, zGv;
    int zdiv;
    int gstride, gdiv;
    int maskStride; float scale;
    int M, N, Kp, epi;
    int rpb, obatch, ldc;
};

#define TC_STAGES 3
#define TC_STAGE_BYTES 32768
#define TC_SMEM (TC_STAGES * TC_STAGE_BYTES)

__global__ __launch_bounds__(256) void tc_gemm_kernel(TcP p) {
    extern __shared__ char dsm[];
    uint32_t sbase = smem_u32(dsm);

    int tid  = threadIdx.x;
    int wid  = tid >> 5;
    int lane = tid & 31;
    int wm = wid >> 2;
    int wn = wid & 3;

    int m0 = blockIdx.y * 128;
    int n0 = blockIdx.x * 128;
    int z  = blockIdx.z;
    int zb = z / p.zdiv;
    int zr = z - zb * p.zdiv;

    const __half* Ab = p.A  + (size_t)zb * p.zA1 + (size_t)zr * p.zA2;
    const __half* Bb = p.Bt + (size_t)zb * p.zB1 + (size_t)zr * p.zB2;

    int kc = tid & 7;
    int rb = tid >> 3;

    float acc[4][4][4];
    #pragma unroll
    for (int i = 0; i < 4; i++)
        #pragma unroll
        for (int j = 0; j < 4; j++)
            #pragma unroll
            for (int e = 0; e < 4; e++) acc[i][j][e] = 0.f;

    int nIter = p.Kp >> 6;

    auto issue = [&](int it) {
        int st = it % TC_STAGES;
        uint32_t sa = sbase + st * TC_STAGE_BYTES;
        uint32_t sb = sa + 16384;
        int k0 = it << 6;
        #pragma unroll
        for (int i = 0; i < 4; i++) {
            int row = rb + i * 32;
            int ra = m0 + row; if (ra > p.M - 1) ra = p.M - 1;
            CP_ASYNC16(sw_addr(sa, row, kc), Ab + (size_t)ra * p.Kp + k0 + kc * 8);
            int rn = n0 + row; if (rn > p.N - 1) rn = p.N - 1;
            CP_ASYNC16(sw_addr(sb, row, kc), Bb + (size_t)rn * p.Kp + k0 + kc * 8);
        }
        CP_COMMIT();
    };

    #pragma unroll
    for (int s = 0; s < TC_STAGES - 1; s++) issue(s);

    int grp = lane >> 3;
    int lr  = lane & 7;

    for (int it = 0; it < nIter; it++) {
        if (it + TC_STAGES - 1 < nIter) {
            issue(it + TC_STAGES - 1);
            CP_WAIT(TC_STAGES - 2);
        } else {
            CP_WAIT(0);
        }
        __syncthreads();

        int st = it % TC_STAGES;
        uint32_t sa = sbase + st * TC_STAGE_BYTES;
        uint32_t sb = sa + 16384;

        #pragma unroll
        for (int kb = 0; kb < 4; kb++) {
            int chA = 2 * kb + (grp >> 1);
            uint32_t a[4][4];
            #pragma unroll
            for (int mi = 0; mi < 4; mi++) {
                int row = wm * 64 + mi * 16 + (grp & 1) * 8 + lr;
                ldsm_x4(a[mi], sw_addr(sa, row, chA));
            }
            uint32_t bf[2][4];
            #pragma unroll
            for (int bi = 0; bi < 2; bi++) {
                int row = wn * 32 + bi * 16 + (grp & 1) * 8 + lr;
                ldsm_x4(bf[bi], sw_addr(sb, row, chA));
            }
            #pragma unroll
            for (int mi = 0; mi < 4; mi++)
                #pragma unroll
                for (int ni = 0; ni < 4; ni++) {
                    int bi = ni >> 1, wh = ni & 1;
                    mma_f16(acc[mi][ni], a[mi], bf[bi][wh], bf[bi][wh + 2]);
                }
        }
        __syncthreads();
    }

    // ---- epilogue ----
    const int* csb  = p.cs  ? p.cs  + (size_t)zb * p.maskStride : nullptr;
    const int* padb = p.pad ? p.pad + (size_t)zb * p.maskStride : nullptr;
    const float* auxz = p.aux ? p.aux + (size_t)zb * p.zAux : nullptr;
    const __half* auxhz = p.auxh ? p.auxh + (size_t)zb * p.zAux : nullptr;
    const float* gvz  = p.gvec ? p.gvec + (size_t)zb * p.zGv : nullptr;
    float* Cz = p.C + (size_t)zb * p.zC1 + (size_t)zr * p.zC2;
    __half* Chz = p.Ch + (size_t)zb * p.zC1 + (size_t)zr * p.zC2;
    int qrow = lane >> 2;
    int qcol = (lane & 3) * 2;
    #pragma unroll
    for (int mi = 0; mi < 4; mi++) {
        #pragma unroll
        for (int half_ = 0; half_ < 2; half_++) {
            int r = m0 + wm * 64 + mi * 16 + half_ * 8 + qrow;
            if (r >= p.M) continue;
            int orow = (r / p.rpb) * p.obatch + (r % p.rpb);
            #pragma unroll
            for (int ni = 0; ni < 4; ni++) {
                int col = n0 + wn * 32 + ni * 8 + qcol;
                if (col >= p.N) continue;
                float v0 = acc[mi][ni][half_ * 2 + 0];
                float v1 = acc[mi][ni][half_ * 2 + 1];
                if (p.epi == EPI_QKV) {
                    float2 ov = make_float2(v0, v1);
                    if (col < H_ * HD_)
                        *(float2*)&p.C[(size_t)orow * (H_ * HD_) + col] = ov;
                    else if (col < H_ * HD_ + HD_)
                        *(float2*)&p.Ck[(size_t)orow * HD_ + (col - H_ * HD_)] = ov;
                    else
                        *(float2*)&p.Cv[(size_t)orow * HD_ + (col - H_ * HD_ - HD_)] = ov;
                    continue;
                } else if (p.epi == EPI_H) {
                    __half2 hv; hv.x = __float2half(v0); hv.y = __float2half(v1);
                    *(__half2*)&Chz[(size_t)orow * p.ldc + col] = hv;
                    continue;
                } else if (p.epi == EPI_GELUMUL_HH) {
                    __half2 ah = *(const __half2*)&auxhz[(size_t)r * p.N + col];
                    __half2 hv;
                    hv.x = __float2half(gelu_tanh(__half2float(ah.x)) * v0);
                    hv.y = __float2half(gelu_tanh(__half2float(ah.y)) * v1);
                    *(__half2*)&Chz[(size_t)orow * p.ldc + col] = hv;
                    continue;
                } else if (p.epi == EPI_SCORES_H) {
                    int csr = csb[r];
                    bool okr = padb[r] != 0;
                    bool ok0 = (csb[col] <= csr) && okr && (padb[col] != 0);
                    bool ok1 = (csb[col + 1] <= csr) && okr && (padb[col + 1] != 0);
                    __half2 hv;
                    hv.x = __float2half(ok0 ? v0 * p.scale : MASK_H_);
                    hv.y = __float2half(ok1 ? v1 * p.scale : MASK_H_);
                    *(__half2*)&Chz[(size_t)orow * p.ldc + col] = hv;
                    continue;
                } else if (p.epi == EPI_RES) {
                    float2 ax = *(const float2*)&auxz[(size_t)r * p.N + col];
                    v0 += ax.x; v1 += ax.y;
                } else if (p.epi == EPI_RES_GATE) {
                    float2 ax = *(const float2*)&auxz[(size_t)r * p.N + col];
                    float2 gx = *(const float2*)&gvz[(size_t)(r / p.gdiv) * p.gstride + col];
                    v0 = ax.x + gx.x * v0;
                    v1 = ax.y + gx.y * v1;
                }
                *(float2*)&Cz[(size_t)orow * p.ldc + col] = make_float2(v0, v1);
            }
        }
    }
}

// ---------------- multi-weight transpose fp32 -> fp16 ----------------
#define WT_MAX 8
struct WtEntry { const float* src; __half* dst; int K, N, nx, blkOff; };
struct WtP { WtEntry e[WT_MAX]; int cnt; };

__global__ void wtrans_multi_kernel(WtP p) {
    int bx = blockIdx.x;
    int i = p.cnt - 1;
    while (i > 0 && bx < p.e[i].blkOff) i--;
    WtEntry e = p.e[i];
    int local = bx - e.blkOff;
    int n0 = (local % e.nx) * 32;
    int k0 = (local / e.nx) * 64;

    __shared__ float t[64][33];
    int tx = threadIdx.x, ty = threadIdx.y;
    #pragma unroll
    for (int j = 0; j < 8; j++)
        t[ty + j * 8][tx] = e.src[(size_t)(k0 + ty + j * 8) * e.N + n0 + tx];
    __syncthreads();
    #pragma unroll
    for (int j = 0; j < 4; j++) {
        int nl = j * 8 + ty;
        __half2 hv;
        hv.x = __float2half(t[2 * tx][nl]);
        hv.y = __float2half(t[2 * tx + 1][nl]);
        *(__half2*)&e.dst[(size_t)(n0 + nl) * e.K + k0 + 2 * tx] = hv;
    }
}

// batched V transpose (z over B)
__global__ void wtrans_kernel(const float* __restrict__ W, __half* __restrict__ out,
                              int K, int N, size_t inZ, size_t outZ) {
    W   += blockIdx.z * inZ;
    out += blockIdx.z * outZ;
    __shared__ float t[64][33];
    int k0 = blockIdx.y * 64, n0 = blockIdx.x * 32;
    int tx = threadIdx.x, ty = threadIdx.y;
    #pragma unroll
    for (int i = 0; i < 8; i++)
        t[ty + i * 8][tx] = W[(size_t)(k0 + ty + i * 8) * N + n0 + tx];
    __syncthreads();
    #pragma unroll
    for (int j = 0; j < 4; j++) {
        int nl = j * 8 + ty;
        __half2 hv;
        hv.x = __float2half(t[2 * tx][nl]);
        hv.y = __float2half(t[2 * tx + 1][nl]);
        *(__half2*)&out[(size_t)(n0 + nl) * K + k0 + 2 * tx] = hv;
    }
}

// merged RoPE (Q then K ranges) -> fp16
__global__ void rope_qk_kernel(const float* __restrict__ q, const float* __restrict__ k,
                               const int* __restrict__ pos,
                               __half* __restrict__ qr, __half* __restrict__ kr) {
    const long NQ = (long)B_ * H_ * S_ * 128;
    const long NK = (long)B_ * S_ * 128;
    long idx = blockIdx.x * (long)blockDim.x + threadIdx.x;
    if (idx >= NQ + NK) return;
    if (idx < NQ) {
        int i = (int)(idx & 127);
        long t = idx >> 7;
        int s = (int)(t % S_); t /= S_;
        int h = (int)(t % H_);
        int b = (int)(t / H_);
        const float* base = q + ((size_t)(b * S_ + s) * H_ + h) * HD_;
        float x1 = base[i], x2 = base[i + 128];
        float f = (float)pos[b * S_ + s] * expf(-((float)i / 128.0f) * 9.210340371976184f);
        float sn, c; sincosf(f, &sn, &c);
        __half* ob = qr + ((size_t)(b * H_ + h) * S_ + s) * HD_;
        ob[i]       = __float2half(x1 * c - x2 * sn);
        ob[i + 128] = __float2half(x2 * c + x1 * sn);
    } else {
        idx -= NQ;
        int i = (int)(idx & 127);
        long t = idx >> 7;
        int s = (int)(t % S_);
        int b = (int)(t / S_);
        const float* base = k + (size_t)(b * S_ + s) * HD_;
        float x1 = base[i], x2 = base[i + 128];
        float f = (float)pos[b * S_ + s] * expf(-((float)i / 128.0f) * 9.210340371976184f);
        float sn, c; sincosf(f, &sn, &c);
        __half* ob = kr + (size_t)(b * S_ + s) * HD_;
        ob[i]       = __float2half(x1 * c - x2 * sn);
        ob[i + 128] = __float2half(x2 * c + x1 * sn);
    }
}

// elementwise gelu-mul (stream-1 fused gate|up)
__global__ void ew_gelumul_kernel(const __half* __restrict__ gu, __half* __restrict__ out,
                                  int M, int F) {
    long idx = blockIdx.x * (long)blockDim.x + threadIdx.x;
    if (idx >= (long)M * F) return;
    int r = (int)(idx / F), j = (int)(idx % F);
    const __half* g = gu + (size_t)r * 2 * F;
    out[(size_t)r * F + j] =
        __float2half(gelu_tanh(__half2float(g[j])) * __half2float(g[F + j]));
}

// merged mod GEMV
__global__ void mod2_kernel(const float* __restrict__ cond,
                            const float* __restrict__ W0, const float* __restrict__ b0, float* __restrict__ o0,
                            const float* __restrict__ W1, const float* __restrict__ b1, float* __restrict__ o1,
                            int D, int N) {
    const float* W = blockIdx.z ? W1 : W0;
    const float* bias = blockIdx.z ? b1 : b0;
    float* out = blockIdx.z ? o1 : o0;
    __shared__ float red[256];
    int tid = threadIdx.x;
    int j = blockIdx.x * 64 + (tid & 63);
    int ks = tid >> 6;
    int b = blockIdx.y;
    const float* c = cond + (size_t)b * D;
    int kseg = D >> 2;
    int kbeg = ks * kseg;
    float s = 0.f;
    for (int kk = kbeg; kk < kbeg + kseg; kk++)
        s += c[kk] * W[(size_t)kk * N + j];
    red[tid] = s;
    __syncthreads();
    if (ks == 0)
        out[(size_t)b * N + j] = bias[j] + red[tid] + red[tid + 64] + red[tid + 128] + red[tid + 192];
}

// parallel prefix scan (block per batch)
__global__ void scan_par_kernel(const int* __restrict__ pad, const int* __restrict__ att,
                                int* __restrict__ pos, int* __restrict__ cs) {
    __shared__ int sp[1024];
    __shared__ int sa[1024];
    int b = blockIdx.x;
    int t = threadIdx.x;
    int vp = 0, va = 0;
    if (t < S_) {
        vp = pad[b * S_ + t];
        va = att[b * S_ + t];
    }
    sp[t] = vp; sa[t] = va;
    __syncthreads();
    #pragma unroll
    for (int off = 1; off < 1024; off <<= 1) {
        int ap = 0, aa = 0;
        if (t >= off) { ap = sp[t - off]; aa = sa[t - off]; }
        __syncthreads();
        sp[t] += ap; sa[t] += aa;
        __syncthreads();
    }
    if (t < S_) {
        pos[b * S_ + t] = sp[t] - 1;
        cs[b * S_ + t] = sa[t];
    }
}

// merged RMSNorm (two tensors, row-routed) -> fp16; float4 loads + shuffle reduce
__global__ void rmsnorm2_kernel(const float* __restrict__ xA, __half* __restrict__ oA,
                                const float* __restrict__ wA, int wsA, int DA, int rpbA, int MA,
                                const float* __restrict__ xB, __half* __restrict__ oB,
                                const float* __restrict__ wB, int wsB, int DB, int rpbB) {
    long row = blockIdx.x;
    const float* xp; __half* op; const float* wp; int D;
    if (row < MA) {
        xp = xA + row * (long)DA; op = oA + row * (long)DA;
        wp = wA + (size_t)(row / rpbA) * wsA; D = DA;
    } else {
        long r2 = row - MA;
        xp = xB + r2 * (long)DB; op = oB + r2 * (long)DB;
        wp = wB + (size_t)(r2 / rpbB) * wsB; D = DB;
    }
    int n4 = D >> 2;
    const float4* x4 = (const float4*)xp;
    float ss = 0.f;
    for (int i = threadIdx.x; i < n4; i += blockDim.x) {
        float4 v = x4[i];
        ss += v.x * v.x + v.y * v.y + v.z * v.z + v.w * v.w;
    }
    #pragma unroll
    for (int o = 16; o > 0; o >>= 1) ss += __shfl_xor_sync(0xffffffffu, ss, o);
    __shared__ float warps[8];
    if ((threadIdx.x & 31) == 0) warps[threadIdx.x >> 5] = ss;
    __syncthreads();
    float tot = 0.f;
    #pragma unroll
    for (int w = 0; w < 8; w++) tot += warps[w];
    float r = rsqrtf(tot / (float)D + EPS_);
    const float4* w4 = (const float4*)wp;
    for (int i = threadIdx.x; i < n4; i += blockDim.x) {
        float4 v = x4[i];
        float4 wv = w4[i];
        __half2 h0, h1;
        h0.x = __float2half(v.x * r * (1.0f + wv.x));
        h0.y = __float2half(v.y * r * (1.0f + wv.y));
        h1.x = __float2half(v.z * r * (1.0f + wv.z));
        h1.y = __float2half(v.w * r * (1.0f + wv.w));
        *(__half2*)&op[i * 4]     = h0;
        *(__half2*)&op[i * 4 + 2] = h1;
    }
}

// row softmax on fp16 in-place; half2 loads + shuffle reduce (row = 832 = 416 half2)
__global__ void softmax_h_kernel(__half* __restrict__ probs) {
    __half2* p2 = (__half2*)(probs + (size_t)blockIdx.x * S_);
    const int N2 = S_ / 2;   // 416
    int tid = threadIdx.x;
    bool has1 = (tid + 256) < N2;
    float2 v0 = __half22float2(p2[tid]);
    float2 v1 = make_float2(0.f, 0.f);
    if (has1) v1 = __half22float2(p2[tid + 256]);

    float m = fmaxf(v0.x, v0.y);
    if (has1) m = fmaxf(m, fmaxf(v1.x, v1.y));
    #pragma unroll
    for (int o = 16; o > 0; o >>= 1) m = fmaxf(m, __shfl_xor_sync(0xffffffffu, m, o));
    __shared__ float sw[8];
    if ((tid & 31) == 0) sw[tid >> 5] = m;
    __syncthreads();
    float mm = sw[0];
    #pragma unroll
    for (int w = 1; w < 8; w++) mm = fmaxf(mm, sw[w]);

    v0.x = expf(v0.x - mm); v0.y = expf(v0.y - mm);
    float s = v0.x + v0.y;
    if (has1) {
        v1.x = expf(v1.x - mm); v1.y = expf(v1.y - mm);
        s += v1.x + v1.y;
    }
    #pragma unroll
    for (int o = 16; o > 0; o >>= 1) s += __shfl_xor_sync(0xffffffffu, s, o);
    __syncthreads();
    if ((tid & 31) == 0) sw[tid >> 5] = s;
    __syncthreads();
    float tot = 0.f;
    #pragma unroll
    for (int w = 0; w < 8; w++) tot += sw[w];
    float inv = 1.0f / tot;

    __half2 o0; o0.x = __float2half(v0.x * inv); o0.y = __float2half(v0.y * inv);
    p2[tid] = o0;
    if (has1) {
        __half2 o1; o1.x = __float2half(v1.x * inv); o1.y = __float2half(v1.y * inv);
        p2[tid + 256] = o1;
    }
}

// ---------------- host helper ----------------
struct TcArgs {
    const __half* A; const __half* Bt;
    float* C; __half* Ch = nullptr;
    int M = 0, N = 0, Kp = 0, epi = 0;
    const float* aux = nullptr;
    int rpb = 0, obatch = 0, ldc = 0;
    int zcount = 1, zdiv = 1;
    size_t zA1 = 0, zA2 = 0, zB1 = 0, zB2 = 0, zC1 = 0, zC2 = 0, zAux = 0, zGv = 0;
    const int* cs = nullptr; const int* pad = nullptr;
    int maskStride = 0; float scale = 1.0f;
    const float* gvec = nullptr; int gstride = 0, gdiv = 1;
    float* Ck = nullptr; float* Cv = nullptr;
    const __half* auxh = nullptr;
    cudaStream_t st = 0;
};

static void launch_tc(const TcArgs& a) {
    cudaFuncSetAttribute(tc_gemm_kernel, cudaFuncAttributeMaxDynamicSharedMemorySize, TC_SMEM);
    TcP p;
    p.A = a.A; p.Bt = a.Bt; p.C = a.C; p.Ch = a.Ch; p.Ck = a.Ck; p.Cv = a.Cv;
    p.aux = a.aux; p.auxh = a.auxh; p.gvec = a.gvec;
    p.cs = a.cs; p.pad = a.pad;
    p.zA1 = a.zA1; p.zA2 = a.zA2; p.zB1 = a.zB1; p.zB2 = a.zB2;
    p.zC1 = a.zC1; p.zC2 = a.zC2; p.zAux = a.zAux; p.zGv = a.zGv;
    p.zdiv = a.zdiv; p.gstride = a.gstride; p.gdiv = a.gdiv;
    p.maskStride = a.maskStride; p.scale = a.scale;
    p.M = a.M; p.N = a.N; p.Kp = a.Kp; p.epi = a.epi;
    p.rpb = a.rpb ? a.rpb : a.M; p.obatch = a.obatch; p.ldc = a.ldc ? a.ldc : a.N;
    dim3 grid((a.N + 127) / 128, (a.M + 127) / 128, a.zcount);
    tc_gemm_kernel<<<grid, 256, TC_SMEM, a.st>>>(p);
}

struct WtBuild {
    WtP p;
    int total = 0;
    WtBuild() { p.cnt = 0; }
    void add(const float* src, __half* dst, int K, int N) {
        WtEntry& e = p.e[p.cnt++];
        e.src = src; e.dst = dst; e.K = K; e.N = N;
        e.nx = N / 32;
        e.blkOff = total;
        total += (N / 32) * (K / 64);
    }
    void launch(cudaStream_t st) {
        wtrans_multi_kernel<<<total, dim3(32, 8), 0, st>>>(p);
    }
};

extern "C" void kernel_launch(void* const* d_in, const int* in_sizes, int n_in,
                              void* d_out, int out_size) {
    const float* x0         = (const float*)d_in[0];
    const float* x1         = (const float*)d_in[1];
    const float* cond1      = (const float*)d_in[2];
    const float* w_q0       = (const float*)d_in[3];
    const float* w_k0       = (const float*)d_in[4];
    const float* w_v0       = (const float*)d_in[5];
    const float* w_o0       = (const float*)d_in[6];
    const float* norm1_w0   = (const float*)d_in[7];
    const float* norm2_w0   = (const float*)d_in[8];
    const float* w_gate0    = (const float*)d_in[9];
    const float* w_up0      = (const float*)d_in[10];
    const float* w_down0    = (const float*)d_in[11];
    const float* w_q1       = (const float*)d_in[12];
    const float* w_k1       = (const float*)d_in[13];
    const float* w_v1       = (const float*)d_in[14];
    const float* w_o1       = (const float*)d_in[15];
    const float* ada_in_w1  = (const float*)d_in[16];
    const float* ada_in_b1  = (const float*)d_in[17];
    const float* ada_post_w1= (const float*)d_in[18];
    const float* ada_post_b1= (const float*)d_in[19];
    const float* w_gate1    = (const float*)d_in[20];
    const float* w_up1      = (const float*)d_in[21];
    const float* w_down1    = (const float*)d_in[22];
    const int*   pad_masks  = (const int*)d_in[23];
    const int*   att_masks  = (const int*)d_in[24];

    float* out0 = (float*)d_out;
    float* out1 = out0 + (size_t)B_ * S1_ * D0_;

    float *modin, *modpost, *q, *k, *v, *r0, *r1;
    int *pos, *cs;
    __half *hc0, *hc1, *qr, *kr, *vt, *ph, *atth, *yc0, *yc1;
    __half *gu0hg, *gu0h, *gu1h2, *gu1h;
    __half *wqkv0t, *wqkv1t, *wo0t, *wg0t, *wu0t, *wd0t, *wo1t, *wgu1t, *wd1t;
    cudaGetSymbolAddress((void**)&modin, g_mod_in);
    cudaGetSymbolAddress((void**)&modpost, g_mod_post);
    cudaGetSymbolAddress((void**)&q, g_q);
    cudaGetSymbolAddress((void**)&k, g_k);
    cudaGetSymbolAddress((void**)&v, g_v);
    cudaGetSymbolAddress((void**)&r0, g_r0);
    cudaGetSymbolAddress((void**)&r1, g_r1);
    cudaGetSymbolAddress((void**)&pos, g_pos);
    cudaGetSymbolAddress((void**)&cs, g_cs);
    cudaGetSymbolAddress((void**)&hc0, g_hc0);
    cudaGetSymbolAddress((void**)&hc1, g_hc1);
    cudaGetSymbolAddress((void**)&qr, g_qr);
    cudaGetSymbolAddress((void**)&kr, g_kr);
    cudaGetSymbolAddress((void**)&vt, g_vt);
    cudaGetSymbolAddress((void**)&ph, g_ph);
    cudaGetSymbolAddress((void**)&atth, g_atth);
    cudaGetSymbolAddress((void**)&yc0, g_yc0);
    cudaGetSymbolAddress((void**)&yc1, g_yc1);
    cudaGetSymbolAddress((void**)&gu0hg, g_gu0hg);
    cudaGetSymbolAddress((void**)&gu0h, g_gu0h);
    cudaGetSymbolAddress((void**)&gu1h2, g_gu1h2);
    cudaGetSymbolAddress((void**)&gu1h, g_gu1h);
    cudaGetSymbolAddress((void**)&wqkv0t, g_wqkv0t);
    cudaGetSymbolAddress((void**)&wqkv1t, g_wqkv1t);
    cudaGetSymbolAddress((void**)&wo0t, g_wo0t);
    cudaGetSymbolAddress((void**)&wg0t, g_wg0t);
    cudaGetSymbolAddress((void**)&wu0t, g_wu0t);
    cudaGetSymbolAddress((void**)&wd0t, g_wd0t);
    cudaGetSymbolAddress((void**)&wo1t, g_wo1t);
    cudaGetSymbolAddress((void**)&wgu1t, g_wgu1t);
    cudaGetSymbolAddress((void**)&wd1t, g_wd1t);

    const int M0 = B_ * S1_;   // 3072
    const int M1 = B_ * S2_;   // 256

    // ---- side stream + events (created once, outside capture) ----
    static cudaStream_t s2 = nullptr;
    static cudaEvent_t evFork = nullptr, evJoin = nullptr, evAtth = nullptr, evDone1 = nullptr;
    if (!s2) {
        cudaStreamCreate(&s2);
        cudaEventCreateWithFlags(&evFork, cudaEventDisableTiming);
        cudaEventCreateWithFlags(&evJoin, cudaEventDisableTiming);
        cudaEventCreateWithFlags(&evAtth, cudaEventDisableTiming);
        cudaEventCreateWithFlags(&evDone1, cudaEventDisableTiming);
    }

    // fork: merged conversion of late-consumed weights on side stream
    cudaEventRecord(evFork, 0);
    cudaStreamWaitEvent(s2, evFork, 0);
    {
        WtBuild wb;
        wb.add(w_o0,    wo0t, H_ * HD_, D0_);
        wb.add(w_gate0, wg0t, D0_, F0_);
        wb.add(w_up0,   wu0t, D0_, F0_);
        wb.add(w_down0, wd0t, F0_, D0_);
        wb.add(w_o1,    wo1t, H_ * HD_, D1_);
        wb.add(w_gate1, wgu1t, D1_, F1_);
        wb.add(w_up1,   wgu1t + (size_t)F1_ * D1_, D1_, F1_);
        wb.add(w_down1, wd1t, F1_, D1_);
        wb.launch(s2);
    }
    cudaEventRecord(evJoin, s2);

    // main stream: merged QKV weight conversion
    {
        WtBuild wb;
        wb.add(w_q0, wqkv0t, D0_, H_ * HD_);
        wb.add(w_k0, wqkv0t + (size_t)(H_ * HD_) * D0_, D0_, HD_);
        wb.add(w_v0, wqkv0t + (size_t)(H_ * HD_ + HD_) * D0_, D0_, HD_);
        wb.add(w_q1, wqkv1t, D1_, H_ * HD_);
        wb.add(w_k1, wqkv1t + (size_t)(H_ * HD_) * D1_, D1_, HD_);
        wb.add(w_v1, wqkv1t + (size_t)(H_ * HD_ + HD_) * D1_, D1_, HD_);
        wb.launch(0);
    }

    // ---- adaLN modulation (merged) + parallel scans ----
    {
        dim3 mg(2 * D1_ / 64, B_, 2);
        mod2_kernel<<<mg, 256>>>(cond1, ada_in_w1, ada_in_b1, modin,
                                 ada_post_w1, ada_post_b1, modpost, D1_, 2 * D1_);
    }
    scan_par_kernel<<<B_, 1024>>>(pad_masks, att_masks, pos, cs);

    // ---- input norms (merged) -> fp16 ----
    rmsnorm2_kernel<<<M0 + M1, 256>>>(x0, hc0, norm1_w0, 0, D0_, S1_, M0,
                                      x1, hc1, modin, 2 * D1_, D1_, S2_);

    // ---- fused QKV projections ----
    { TcArgs a{hc0, wqkv0t, q, nullptr, M0, NQKV_, D0_, EPI_QKV};
      a.Ck = k; a.Cv = v;
      a.rpb = S1_; a.obatch = S_; launch_tc(a); }
    { TcArgs a{hc1, wqkv1t, q + (size_t)S1_ * H_ * HD_, nullptr, M1, NQKV_, D1_, EPI_QKV};
      a.Ck = k + (size_t)S1_ * HD_; a.Cv = v + (size_t)S1_ * HD_;
      a.rpb = S2_; a.obatch = S_; launch_tc(a); }

    // ---- merged RoPE + V transpose ----
    {
        long ntot = (long)B_ * H_ * S_ * 128 + (long)B_ * S_ * 128;
        rope_qk_kernel<<<(unsigned)((ntot + 255) / 256), 256>>>(q, k, pos, qr, kr);
        dim3 vg(HD_ / 32, S_ / 64, B_);
        wtrans_kernel<<<vg, dim3(32, 8)>>>(v, vt, S_, HD_, (size_t)S_ * HD_, (size_t)HD_ * S_);
    }

    // ---- scores = Q K^T * scale, masked -> fp16 ph (z = B*H) ----
    { TcArgs a{qr, kr, nullptr, ph, S_, S_, HD_, EPI_SCORES_H};
      a.zcount = B_ * H_; a.zdiv = H_;
      a.zA1 = (size_t)H_ * S_ * HD_; a.zA2 = (size_t)S_ * HD_;
      a.zB1 = (size_t)S_ * HD_;
      a.zC1 = (size_t)H_ * S_ * S_; a.zC2 = (size_t)S_ * S_;
      a.cs = cs; a.pad = pad_masks; a.maskStride = S_; a.scale = 0.0625f;
      launch_tc(a); }

    softmax_h_kernel<<<B_ * H_ * S_, 256>>>(ph);

    // ---- PV (z = B*H) -> atth fp16 ----
    { TcArgs a{ph, vt, nullptr, atth, S_, HD_, S_, EPI_H};
      a.ldc = H_ * HD_;
      a.zcount = B_ * H_; a.zdiv = H_;
      a.zA1 = (size_t)H_ * S_ * S_; a.zA2 = (size_t)S_ * S_;
      a.zB1 = (size_t)HD_ * S_;
      a.zC1 = (size_t)S_ * H_ * HD_; a.zC2 = (size_t)HD_;
      launch_tc(a); }
    cudaEventRecord(evAtth, 0);

    // ======== SIDE STREAM: entire stream-1 chain (fills stream-0 tail waves) ========
    cudaStreamWaitEvent(s2, evAtth, 0);
    { TcArgs a{atth + (size_t)S1_ * H_ * HD_, wo1t, r1, nullptr, S2_, D1_, H_ * HD_, EPI_RES_GATE};
      a.aux = x1;
      a.zcount = B_;
      a.zA1 = (size_t)S_ * H_ * HD_; a.zC1 = (size_t)S2_ * D1_; a.zAux = (size_t)S2_ * D1_;
      a.gvec = modin + D1_; a.zGv = (size_t)2 * D1_; a.gdiv = S2_; a.gstride = 0;
      a.st = s2; launch_tc(a); }
    rmsnorm2_kernel<<<M1, 256, 0, s2>>>(nullptr, nullptr, nullptr, 0, 4, 1, 0,
                                        r1, yc1, modpost, 2 * D1_, D1_, S2_);
    { TcArgs a{yc1, wgu1t, nullptr, gu1h2, M1, 2 * F1_, D1_, EPI_H}; a.st = s2; launch_tc(a); }
    {
        long n = (long)M1 * F1_;
        ew_gelumul_kernel<<<(unsigned)((n + 255) / 256), 256, 0, s2>>>(gu1h2, gu1h, M1, F1_);
    }
    { TcArgs a{gu1h, wd1t, out1, nullptr, M1, D1_, F1_, EPI_RES_GATE};
      a.aux = r1;
      a.gvec = modpost + D1_; a.gstride = 2 * D1_; a.gdiv = S2_;
      a.st = s2; launch_tc(a); }
    cudaEventRecord(evDone1, s2);

    // ======== MAIN STREAM: stream-0 chain ========
    cudaStreamWaitEvent(0, evJoin, 0);

    { TcArgs a{atth, wo0t, r0, nullptr, S1_, D0_, H_ * HD_, EPI_RES};
      a.aux = x0;
      a.zcount = B_;
      a.zA1 = (size_t)S_ * H_ * HD_; a.zC1 = (size_t)S1_ * D0_; a.zAux = (size_t)S1_ * D0_;
      launch_tc(a); }

    rmsnorm2_kernel<<<M0, 256>>>(r0, yc0, norm2_w0, 0, D0_, S1_, M0,
                                 nullptr, nullptr, nullptr, 0, 4, 1);

    { TcArgs a{yc0, wg0t, nullptr, gu0hg, M0, F0_, D0_, EPI_H}; launch_tc(a); }
    { TcArgs a{yc0, wu0t, nullptr, gu0h, M0, F0_, D0_, EPI_GELUMUL_HH}; a.auxh = gu0hg; launch_tc(a); }
    { TcArgs a{gu0h, wd0t, out0, nullptr, M0, D0_, F0_, EPI_RES}; a.aux = r0; launch_tc(a); }

    // final join: stream-1 chain must complete before harness reads d_out
    cudaStreamWaitEvent(0, evDone1, 0);
}